// round 2
// baseline (speedup 1.0000x reference)
#include <cuda_runtime.h>
#include <math.h>

// Problem constants
#define BATCH 4
#define TQN   9          // frames incl. CLS-ish last frame
#define TFR   8          // spatial frames
#define HWN   1024       // 32x32
#define DIMN  256
#define NHN   8
#define DHN   32
#define MLPD  1024
#define NROWS    (BATCH*TQN*HWN)   // 36864
#define NROWS_SP (BATCH*TFR*HWN)   // 32768
#define SCALE 0.17677669529663687f // 1/sqrt(32)

// ---------------- scratch (static device memory; no allocations) -----------
__device__ float g_xn[NROWS*DIMN];
__device__ float g_q [NROWS*DIMN];
__device__ float g_k [NROWS*DIMN];
__device__ float g_v [NROWS*DIMN];
__device__ float g_o [NROWS*DIMN];
__device__ float g_x [NROWS*DIMN];
__device__ float g_h [(long)NROWS*MLPD];

// ---------------- LayerNorm: one block (256 thr) per row --------------------
// remap==1: input row r maps to query row (b*9+t)*1024+hw with r=(b*8+t)*1024+hw
__global__ void ln_kernel(const float* __restrict__ in, const float* __restrict__ g,
                          const float* __restrict__ bta, float* __restrict__ out, int remap)
{
    int r = blockIdx.x;
    long ir = r;
    if (remap) { int b = r >> 13, t = (r >> 10) & 7, hw = r & 1023;
                 ir = ((long)(b * 9 + t) << 10) + hw; }
    float v = in[ir * DIMN + threadIdx.x];
    __shared__ float sbuf[40];
    float s = v, q = v * v;
    #pragma unroll
    for (int o = 16; o; o >>= 1) { s += __shfl_xor_sync(~0u, s, o); q += __shfl_xor_sync(~0u, q, o); }
    int w = threadIdx.x >> 5;
    if ((threadIdx.x & 31) == 0) { sbuf[w] = s; sbuf[8 + w] = q; }
    __syncthreads();
    if (threadIdx.x < 32) {
        s = (threadIdx.x < 8) ? sbuf[threadIdx.x] : 0.f;
        q = (threadIdx.x < 8) ? sbuf[8 + threadIdx.x] : 0.f;
        #pragma unroll
        for (int o = 4; o; o >>= 1) { s += __shfl_xor_sync(~0u, s, o); q += __shfl_xor_sync(~0u, q, o); }
        if (threadIdx.x == 0) { sbuf[32] = s; sbuf[33] = q; }
    }
    __syncthreads();
    float mean = sbuf[32] * (1.f / 256.f);
    float var  = sbuf[33] * (1.f / 256.f) - mean * mean;
    out[(long)r * DIMN + threadIdx.x] =
        (v - mean) * rsqrtf(var + 1e-5f) * g[threadIdx.x] + bta[threadIdx.x];
}

// ---------------- GEMM: C[N,M] = A[N,K] @ W[K,M] + bias (+res)(+gelu) -------
// 128x128 tile, BK=8, 256 threads, 8x8 micro-tile.
// remap==1: output/residual row index gets the spatial (b,8t,hw)->(b,9t,hw) map.
#define BM 128
#define BN 128
#define BK 8
__global__ void gemm_kernel(const float* __restrict__ A, const float* __restrict__ W,
                            const float* __restrict__ bias, const float* __restrict__ res,
                            float* __restrict__ out, int M, int K, int act, int remap)
{
    __shared__ float As[BK][BM + 4];
    __shared__ float Bs[BK][BN];
    int tid = threadIdx.x;
    int tx = tid & 15, ty = tid >> 4;
    long rowBase = (long)blockIdx.y * BM;
    int  colBase = blockIdx.x * BN;
    const float* Aptr = A + rowBase * K;
    const float* Wptr = W + colBase;
    float acc[8][8];
    #pragma unroll
    for (int i = 0; i < 8; i++)
        #pragma unroll
        for (int j = 0; j < 8; j++) acc[i][j] = 0.f;

    for (int k0 = 0; k0 < K; k0 += BK) {
        #pragma unroll
        for (int i = 0; i < 4; i++) {
            int idx = tid + i * 256;            // 0..1023
            int m = idx >> 3, kk = idx & 7;
            As[kk][m] = __ldg(&Aptr[(long)m * K + k0 + kk]);
        }
        #pragma unroll
        for (int i = 0; i < 4; i++) {
            int idx = tid + i * 256;
            int kk = idx >> 7, n = idx & 127;
            Bs[kk][n] = __ldg(&Wptr[(long)(k0 + kk) * M + n]);
        }
        __syncthreads();
        #pragma unroll
        for (int kk = 0; kk < BK; kk++) {
            float a[8], b[8];
            #pragma unroll
            for (int i = 0; i < 4; i++) { a[i] = As[kk][ty * 4 + i]; a[4 + i] = As[kk][64 + ty * 4 + i]; }
            #pragma unroll
            for (int j = 0; j < 4; j++) { b[j] = Bs[kk][tx * 4 + j]; b[4 + j] = Bs[kk][64 + tx * 4 + j]; }
            #pragma unroll
            for (int i = 0; i < 8; i++)
                #pragma unroll
                for (int j = 0; j < 8; j++)
                    acc[i][j] += a[i] * b[j];
        }
        __syncthreads();
    }
    #pragma unroll
    for (int i = 0; i < 8; i++) {
        long m = rowBase + ((i < 4) ? (ty * 4 + i) : (64 + ty * 4 + (i - 4)));
        long om = m;
        if (remap) { int b = (int)(m >> 13), t = (int)((m >> 10) & 7), hw = (int)(m & 1023);
                     om = ((long)(b * 9 + t) << 10) + hw; }
        #pragma unroll
        for (int j = 0; j < 8; j++) {
            int n = colBase + ((j < 4) ? (tx * 4 + j) : (64 + tx * 4 + (j - 4)));
            float v = acc[i][j] + bias[n];
            if (act == 1) v = 0.5f * v * (1.f + erff(v * 0.70710678118654752f));
            if (res) v += res[om * M + n];
            out[om * M + n] = v;
        }
    }
}

// ---------------- Spatial windowed attention (9 neighbors) ------------------
// One block per pixel-token (compact row r in [0,32768)); warp w = head w,
// lane d = head dim d. Q/K/V in compact-row layout.
__global__ void sattn_kernel(const float* __restrict__ Q, const float* __restrict__ K,
                             const float* __restrict__ V, float* __restrict__ O)
{
    int r = blockIdx.x;
    int bt = r >> 10, pix = r & 1023;
    int y = pix >> 5, x = pix & 31;
    int c = threadIdx.x;
    float qv = Q[(long)r * 256 + c];
    float sc[9];
    #pragma unroll
    for (int n = 0; n < 9; n++) {
        int dy = n / 3 - 1, dx = n % 3 - 1;
        int ny = y + dy, nx = x + dx;
        bool ok = ((unsigned)ny < 32u) && ((unsigned)nx < 32u);
        float p = 0.f;
        if (ok) p = qv * K[(((long)(bt << 10) + (ny << 5) + nx) << 8) + c];
        #pragma unroll
        for (int o = 16; o; o >>= 1) p += __shfl_xor_sync(~0u, p, o);
        sc[n] = ok ? p * SCALE : -1e9f;
    }
    float mx = sc[0];
    #pragma unroll
    for (int n = 1; n < 9; n++) mx = fmaxf(mx, sc[n]);
    float den = 0.f;
    #pragma unroll
    for (int n = 0; n < 9; n++) { sc[n] = expf(sc[n] - mx); den += sc[n]; }
    float inv = 1.f / den;
    float acc = 0.f;
    #pragma unroll
    for (int n = 0; n < 9; n++) {
        int dy = n / 3 - 1, dx = n % 3 - 1;
        int ny = y + dy, nx = x + dx;
        if (((unsigned)ny < 32u) && ((unsigned)nx < 32u))
            acc += sc[n] * inv * V[(((long)(bt << 10) + (ny << 5) + nx) << 8) + c];
    }
    O[(long)r * 256 + c] = acc;
}

// ---------------- copy CLS/last frame (t=8) query -> X ----------------------
__global__ void copy8_kernel(const float* __restrict__ q, float* __restrict__ X)
{
    long idx = (long)blockIdx.x * 256 + threadIdx.x;   // 4*1024*256 total
    int b = (int)(idx >> 18);
    long rem = idx & 262143;
    long off = ((long)(b * 9 + 8)) * 262144 + rem;
    X[off] = q[off];
}

// ---------------- RoPE in-place on temporal q,k -----------------------------
__global__ void rope_kernel(float* __restrict__ Q, float* __restrict__ K)
{
    long idx = (long)blockIdx.x * 256 + threadIdx.x;   // NROWS*128 pairs
    long row = idx >> 7;
    int pr = (int)(idx & 127);
    int h = pr >> 4, i = pr & 15;
    int t = (int)((row >> 10) % 9);
    float invf = powf(10000.f, -(float)(2 * i) / 32.f);
    float ang = (float)t * invf;
    float cs = cosf(ang), sn = sinf(ang);
    long o1 = row * 256 + h * 32 + i, o2 = o1 + 16;
    float q1 = Q[o1], q2 = Q[o2];
    Q[o1] = q1 * cs - q2 * sn;  Q[o2] = q1 * sn + q2 * cs;
    float k1 = K[o1], k2 = K[o2];
    K[o1] = k1 * cs - k2 * sn;  K[o2] = k1 * sn + k2 * cs;
}

// ---------------- Temporal attention: block=(b,hw,h), warp=tq ---------------
__global__ void tattn_kernel(const float* __restrict__ Q, const float* __restrict__ K,
                             const float* __restrict__ V, const unsigned char* __restrict__ mask,
                             float* __restrict__ O)
{
    int blk = blockIdx.x;              // 0..32767
    int h = blk & 7, hw = (blk >> 3) & 1023, b = blk >> 13;
    int tq = threadIdx.x >> 5, lane = threadIdx.x & 31;
    int col = (h << 5) + lane;
    long base = ((long)b * TQN) << 10;
    long qrow = base + ((long)tq << 10) + hw;
    float qv = Q[qrow * 256 + col];
    float sc[9];
    #pragma unroll
    for (int tk = 0; tk < 9; tk++) {
        long krow = base + ((long)tk << 10) + hw;
        float p = qv * K[krow * 256 + col];
        #pragma unroll
        for (int o = 16; o; o >>= 1) p += __shfl_xor_sync(~0u, p, o);
        sc[tk] = mask[tq * 9 + tk] ? -1e9f : p * SCALE;
    }
    float mx = sc[0];
    #pragma unroll
    for (int i = 1; i < 9; i++) mx = fmaxf(mx, sc[i]);
    float den = 0.f;
    #pragma unroll
    for (int i = 0; i < 9; i++) { sc[i] = expf(sc[i] - mx); den += sc[i]; }
    float inv = 1.f / den;
    float acc = 0.f;
    #pragma unroll
    for (int tk = 0; tk < 9; tk++) {
        long krow = base + ((long)tk << 10) + hw;
        acc += sc[tk] * inv * V[krow * 256 + col];
    }
    O[qrow * 256 + col] = acc;
}

// ---------------- CLS frame (t=0): spatial mean, broadcast ------------------
__global__ void cls_kernel(float* __restrict__ X)
{
    int b = blockIdx.x, d = threadIdx.x;
    long base = (long)(b * 9) * HWN * DIMN;
    float s = 0.f;
    #pragma unroll 4
    for (int hw = 0; hw < HWN; hw++) s += X[base + (long)hw * DIMN + d];
    s *= (1.f / 1024.f);
    #pragma unroll 4
    for (int hw = 0; hw < HWN; hw++) X[base + (long)hw * DIMN + d] = s;
}

// ---------------- launch ----------------------------------------------------
extern "C" void kernel_launch(void* const* d_in, const int* in_sizes, int n_in,
                              void* d_out, int out_size)
{
    const float* query = (const float*)d_in[0];
    const unsigned char* tmask = (const unsigned char*)d_in[2];
    const float* sln_g = (const float*)d_in[3];
    const float* sln_b = (const float*)d_in[4];
    const float* s_wq = (const float*)d_in[5];  const float* s_bq = (const float*)d_in[6];
    const float* s_wk = (const float*)d_in[7];  const float* s_bk = (const float*)d_in[8];
    const float* s_wv = (const float*)d_in[9];  const float* s_bv = (const float*)d_in[10];
    const float* s_wo = (const float*)d_in[11]; const float* s_bo = (const float*)d_in[12];
    const float* tln_g = (const float*)d_in[13];
    const float* tln_b = (const float*)d_in[14];
    const float* t_wq = (const float*)d_in[15]; const float* t_bq = (const float*)d_in[16];
    const float* t_wk = (const float*)d_in[17]; const float* t_bk = (const float*)d_in[18];
    const float* t_wv = (const float*)d_in[19]; const float* t_bv = (const float*)d_in[20];
    const float* t_wo = (const float*)d_in[21]; const float* t_bo = (const float*)d_in[22];
    const float* mln_g = (const float*)d_in[23];
    const float* mln_b = (const float*)d_in[24];
    const float* w1 = (const float*)d_in[25];   const float* b1 = (const float*)d_in[26];
    const float* w2 = (const float*)d_in[27];   const float* b2 = (const float*)d_in[28];
    float* out = (float*)d_out;

    float *xn, *q, *k, *v, *o, *x, *h;
    cudaGetSymbolAddress((void**)&xn, g_xn);
    cudaGetSymbolAddress((void**)&q,  g_q);
    cudaGetSymbolAddress((void**)&k,  g_k);
    cudaGetSymbolAddress((void**)&v,  g_v);
    cudaGetSymbolAddress((void**)&o,  g_o);
    cudaGetSymbolAddress((void**)&x,  g_x);
    cudaGetSymbolAddress((void**)&h,  g_h);

    // ---- spatial block ----
    ln_kernel<<<NROWS_SP, 256>>>(query, sln_g, sln_b, xn, 1);
    gemm_kernel<<<dim3(2, NROWS_SP / 128), 256>>>(xn, s_wq, s_bq, nullptr, q, 256, 256, 0, 0);
    gemm_kernel<<<dim3(2, NROWS_SP / 128), 256>>>(xn, s_wk, s_bk, nullptr, k, 256, 256, 0, 0);
    gemm_kernel<<<dim3(2, NROWS_SP / 128), 256>>>(xn, s_wv, s_bv, nullptr, v, 256, 256, 0, 0);
    sattn_kernel<<<NROWS_SP, 256>>>(q, k, v, o);
    gemm_kernel<<<dim3(2, NROWS_SP / 128), 256>>>(o, s_wo, s_bo, query, x, 256, 256, 0, 1);
    copy8_kernel<<<4096, 256>>>(query, x);

    // ---- temporal block ----
    ln_kernel<<<NROWS, 256>>>(x, tln_g, tln_b, xn, 0);
    gemm_kernel<<<dim3(2, NROWS / 128), 256>>>(xn, t_wq, t_bq, nullptr, q, 256, 256, 0, 0);
    gemm_kernel<<<dim3(2, NROWS / 128), 256>>>(xn, t_wk, t_bk, nullptr, k, 256, 256, 0, 0);
    gemm_kernel<<<dim3(2, NROWS / 128), 256>>>(xn, t_wv, t_bv, nullptr, v, 256, 256, 0, 0);
    rope_kernel<<<(NROWS * 128) / 256, 256>>>(q, k);
    tattn_kernel<<<32768, 288>>>(q, k, v, tmask, o);
    gemm_kernel<<<dim3(2, NROWS / 128), 256>>>(o, t_wo, t_bo, x, x, 256, 256, 0, 0);

    // ---- CLS average ----
    cls_kernel<<<4, 256>>>(x);

    // ---- MLP ----
    ln_kernel<<<NROWS, 256>>>(x, mln_g, mln_b, xn, 0);
    gemm_kernel<<<dim3(8, NROWS / 128), 256>>>(xn, w1, b1, nullptr, h, 1024, 256, 1, 0);
    gemm_kernel<<<dim3(2, NROWS / 128), 256>>>(h, w2, b2, x, out, 256, 1024, 0, 0);
}

// round 3
// speedup vs baseline: 1.1687x; 1.1687x over previous
#include <cuda_runtime.h>
#include <math.h>

// Problem constants
#define BATCH 4
#define TQN   9
#define TFR   8
#define HWN   1024
#define DIMN  256
#define NHN   8
#define DHN   32
#define MLPD  1024
#define NROWS    (BATCH*TQN*HWN)   // 36864
#define NROWS_SP (BATCH*TFR*HWN)   // 32768
#define SCALE 0.17677669529663687f

// ---------------- scratch (static device memory; no allocations) -----------
__device__ __align__(16) float g_xn[NROWS*DIMN];
__device__ __align__(16) float g_q [NROWS*DIMN];
__device__ __align__(16) float g_k [NROWS*DIMN];
__device__ __align__(16) float g_v [NROWS*DIMN];
__device__ __align__(16) float g_o [NROWS*DIMN];
__device__ __align__(16) float g_x [NROWS*DIMN];
__device__ __align__(16) float g_h [(long)NROWS*MLPD];
__device__ __align__(16) float g_clsp[BATCH*8*DIMN];

// ---------------- LayerNorm: one block (256 thr) per row --------------------
__global__ void ln_kernel(const float* __restrict__ in, const float* __restrict__ g,
                          const float* __restrict__ bta, float* __restrict__ out, int remap)
{
    int r = blockIdx.x;
    long ir = r;
    if (remap) { int b = r >> 13, t = (r >> 10) & 7, hw = r & 1023;
                 ir = ((long)(b * 9 + t) << 10) + hw; }
    float v = in[ir * DIMN + threadIdx.x];
    __shared__ float sbuf[40];
    float s = v, q = v * v;
    #pragma unroll
    for (int o = 16; o; o >>= 1) { s += __shfl_xor_sync(~0u, s, o); q += __shfl_xor_sync(~0u, q, o); }
    int w = threadIdx.x >> 5;
    if ((threadIdx.x & 31) == 0) { sbuf[w] = s; sbuf[8 + w] = q; }
    __syncthreads();
    if (threadIdx.x < 32) {
        s = (threadIdx.x < 8) ? sbuf[threadIdx.x] : 0.f;
        q = (threadIdx.x < 8) ? sbuf[8 + threadIdx.x] : 0.f;
        #pragma unroll
        for (int o = 4; o; o >>= 1) { s += __shfl_xor_sync(~0u, s, o); q += __shfl_xor_sync(~0u, q, o); }
        if (threadIdx.x == 0) { sbuf[32] = s; sbuf[33] = q; }
    }
    __syncthreads();
    float mean = sbuf[32] * (1.f / 256.f);
    float var  = sbuf[33] * (1.f / 256.f) - mean * mean;
    out[(long)r * DIMN + threadIdx.x] =
        (v - mean) * rsqrtf(var + 1e-5f) * g[threadIdx.x] + bta[threadIdx.x];
}

// ---------------- GEMM: C[N,M] = A[N,K] @ W[K,M] + bias (+res)(+gelu) -------
// 128x128 tile, BK=16, 256 threads, 8x8 micro-tile, double-buffered smem,
// register prefetch, float4 smem reads + float4 epilogue.
#define BM 128
#define BN 128
#define BK 16
__global__ void __launch_bounds__(256, 2)
gemm_kernel(const float* __restrict__ A, const float* __restrict__ W,
            const float* __restrict__ bias, const float* __restrict__ res,
            float* __restrict__ out, int M, int K, int act, int remap)
{
    __shared__ float As[2][BK][BM + 4];   // [k][m], padded
    __shared__ float Bs[2][BK][BN];       // [k][n]
    int tid = threadIdx.x;
    int tx = tid & 15, ty = tid >> 4;
    long rowBase = (long)blockIdx.y * BM;
    int  colBase = blockIdx.x * BN;

    // global load assignments
    int a_r = tid >> 1;            // 0..127 row within tile
    int a_k = (tid & 1) * 8;       // 0 or 8
    int b_k = tid >> 5;            // 0..7
    int b_n = (tid & 31) * 4;      // 0..124
    const float* Arow = A + (rowBase + a_r) * (long)K + a_k;
    const float* Wp   = W + (long)b_k * M + colBase + b_n;

    float acc[8][8];
    #pragma unroll
    for (int i = 0; i < 8; i++)
        #pragma unroll
        for (int j = 0; j < 8; j++) acc[i][j] = 0.f;

    // prologue: load first tile
    float4 pa0 = *(const float4*)(Arow);
    float4 pa1 = *(const float4*)(Arow + 4);
    float4 pb0 = *(const float4*)(Wp);
    float4 pb1 = *(const float4*)(Wp + (long)8 * M);
    {
        As[0][a_k + 0][a_r] = pa0.x; As[0][a_k + 1][a_r] = pa0.y;
        As[0][a_k + 2][a_r] = pa0.z; As[0][a_k + 3][a_r] = pa0.w;
        As[0][a_k + 4][a_r] = pa1.x; As[0][a_k + 5][a_r] = pa1.y;
        As[0][a_k + 6][a_r] = pa1.z; As[0][a_k + 7][a_r] = pa1.w;
        *(float4*)&Bs[0][b_k][b_n]     = pb0;
        *(float4*)&Bs[0][8 + b_k][b_n] = pb1;
    }
    __syncthreads();

    int nk = K / BK;
    for (int it = 0; it < nk; it++) {
        int buf = it & 1;
        if (it + 1 < nk) {
            const float* An = Arow + (it + 1) * BK;
            pa0 = *(const float4*)(An);
            pa1 = *(const float4*)(An + 4);
            const float* Wn = Wp + (long)(it + 1) * BK * M;
            pb0 = *(const float4*)(Wn);
            pb1 = *(const float4*)(Wn + (long)8 * M);
        }
        #pragma unroll
        for (int kk = 0; kk < BK; kk++) {
            float4 a0 = *(const float4*)&As[buf][kk][ty * 4];
            float4 a1 = *(const float4*)&As[buf][kk][64 + ty * 4];
            float4 b0 = *(const float4*)&Bs[buf][kk][tx * 4];
            float4 b1 = *(const float4*)&Bs[buf][kk][64 + tx * 4];
            float a[8] = {a0.x, a0.y, a0.z, a0.w, a1.x, a1.y, a1.z, a1.w};
            float b[8] = {b0.x, b0.y, b0.z, b0.w, b1.x, b1.y, b1.z, b1.w};
            #pragma unroll
            for (int i = 0; i < 8; i++)
                #pragma unroll
                for (int j = 0; j < 8; j++)
                    acc[i][j] += a[i] * b[j];
        }
        if (it + 1 < nk) {
            int nb = buf ^ 1;
            As[nb][a_k + 0][a_r] = pa0.x; As[nb][a_k + 1][a_r] = pa0.y;
            As[nb][a_k + 2][a_r] = pa0.z; As[nb][a_k + 3][a_r] = pa0.w;
            As[nb][a_k + 4][a_r] = pa1.x; As[nb][a_k + 5][a_r] = pa1.y;
            As[nb][a_k + 6][a_r] = pa1.z; As[nb][a_k + 7][a_r] = pa1.w;
            *(float4*)&Bs[nb][b_k][b_n]     = pb0;
            *(float4*)&Bs[nb][8 + b_k][b_n] = pb1;
            __syncthreads();
        }
    }

    // epilogue (vectorized)
    #pragma unroll
    for (int i = 0; i < 8; i++) {
        long m = rowBase + ((i < 4) ? (ty * 4 + i) : (64 + ty * 4 + (i - 4)));
        long om = m;
        if (remap) { int b = (int)(m >> 13), t = (int)((m >> 10) & 7), hw = (int)(m & 1023);
                     om = ((long)(b * 9 + t) << 10) + hw; }
        #pragma unroll
        for (int jj = 0; jj < 2; jj++) {
            int n0 = colBase + jj * 64 + tx * 4;
            float4 bv = *(const float4*)&bias[n0];
            float4 vv;
            vv.x = acc[i][jj * 4 + 0] + bv.x;
            vv.y = acc[i][jj * 4 + 1] + bv.y;
            vv.z = acc[i][jj * 4 + 2] + bv.z;
            vv.w = acc[i][jj * 4 + 3] + bv.w;
            if (act == 1) {
                vv.x = 0.5f * vv.x * (1.f + erff(vv.x * 0.70710678118654752f));
                vv.y = 0.5f * vv.y * (1.f + erff(vv.y * 0.70710678118654752f));
                vv.z = 0.5f * vv.z * (1.f + erff(vv.z * 0.70710678118654752f));
                vv.w = 0.5f * vv.w * (1.f + erff(vv.w * 0.70710678118654752f));
            }
            if (res) {
                float4 rv = *(const float4*)&res[om * M + n0];
                vv.x += rv.x; vv.y += rv.y; vv.z += rv.z; vv.w += rv.w;
            }
            *(float4*)&out[om * M + n0] = vv;
        }
    }
}

// ---------------- Spatial windowed attention (9 neighbors) ------------------
__global__ void sattn_kernel(const float* __restrict__ Q, const float* __restrict__ K,
                             const float* __restrict__ V, float* __restrict__ O)
{
    int r = blockIdx.x;
    int bt = r >> 10, pix = r & 1023;
    int y = pix >> 5, x = pix & 31;
    int c = threadIdx.x;
    float qv = Q[(long)r * 256 + c];
    float sc[9];
    #pragma unroll
    for (int n = 0; n < 9; n++) {
        int dy = n / 3 - 1, dx = n % 3 - 1;
        int ny = y + dy, nx = x + dx;
        bool ok = ((unsigned)ny < 32u) && ((unsigned)nx < 32u);
        float p = 0.f;
        if (ok) p = qv * K[(((long)(bt << 10) + (ny << 5) + nx) << 8) + c];
        #pragma unroll
        for (int o = 16; o; o >>= 1) p += __shfl_xor_sync(~0u, p, o);
        sc[n] = ok ? p * SCALE : -1e9f;
    }
    float mx = sc[0];
    #pragma unroll
    for (int n = 1; n < 9; n++) mx = fmaxf(mx, sc[n]);
    float den = 0.f;
    #pragma unroll
    for (int n = 0; n < 9; n++) { sc[n] = expf(sc[n] - mx); den += sc[n]; }
    float inv = 1.f / den;
    float acc = 0.f;
    #pragma unroll
    for (int n = 0; n < 9; n++) {
        int dy = n / 3 - 1, dx = n % 3 - 1;
        int ny = y + dy, nx = x + dx;
        if (((unsigned)ny < 32u) && ((unsigned)nx < 32u))
            acc += sc[n] * inv * V[(((long)(bt << 10) + (ny << 5) + nx) << 8) + c];
    }
    O[(long)r * 256 + c] = acc;
}

// ---------------- copy CLS/last frame (t=8) query -> X ----------------------
__global__ void copy8_kernel(const float* __restrict__ q, float* __restrict__ X)
{
    long idx = (long)blockIdx.x * 256 + threadIdx.x;
    int b = (int)(idx >> 18);
    long rem = idx & 262143;
    long off = ((long)(b * 9 + 8)) * 262144 + rem;
    X[off] = q[off];
}

// ---------------- RoPE in-place on temporal q,k -----------------------------
__global__ void rope_kernel(float* __restrict__ Q, float* __restrict__ K)
{
    long idx = (long)blockIdx.x * 256 + threadIdx.x;
    long row = idx >> 7;
    int pr = (int)(idx & 127);
    int h = pr >> 4, i = pr & 15;
    int t = (int)((row >> 10) % 9);
    float invf = exp2f(-(float)i * 0.83048202372184058696f); // log2(10000)/16
    float ang = (float)t * invf;
    float cs, sn;
    sincosf(ang, &sn, &cs);
    long o1 = row * 256 + h * 32 + i, o2 = o1 + 16;
    float q1 = Q[o1], q2 = Q[o2];
    Q[o1] = q1 * cs - q2 * sn;  Q[o2] = q1 * sn + q2 * cs;
    float k1 = K[o1], k2 = K[o2];
    K[o1] = k1 * cs - k2 * sn;  K[o2] = k1 * sn + k2 * cs;
}

// ---------------- Temporal attention: block=(b,hw,h), warp=tq ---------------
__global__ void tattn_kernel(const float* __restrict__ Q, const float* __restrict__ K,
                             const float* __restrict__ V, const unsigned char* __restrict__ mask,
                             float* __restrict__ O)
{
    int blk = blockIdx.x;
    int h = blk & 7, hw = (blk >> 3) & 1023, b = blk >> 13;
    int tq = threadIdx.x >> 5, lane = threadIdx.x & 31;
    int col = (h << 5) + lane;
    long base = ((long)b * TQN) << 10;
    long qrow = base + ((long)tq << 10) + hw;
    float qv = Q[qrow * 256 + col];
    float sc[9];
    #pragma unroll
    for (int tk = 0; tk < 9; tk++) {
        long krow = base + ((long)tk << 10) + hw;
        float p = qv * K[krow * 256 + col];
        #pragma unroll
        for (int o = 16; o; o >>= 1) p += __shfl_xor_sync(~0u, p, o);
        sc[tk] = mask[tq * 9 + tk] ? -1e9f : p * SCALE;
    }
    float mx = sc[0];
    #pragma unroll
    for (int i = 1; i < 9; i++) mx = fmaxf(mx, sc[i]);
    float den = 0.f;
    #pragma unroll
    for (int i = 0; i < 9; i++) { sc[i] = expf(sc[i] - mx); den += sc[i]; }
    float inv = 1.f / den;
    float acc = 0.f;
    #pragma unroll
    for (int tk = 0; tk < 9; tk++) {
        long krow = base + ((long)tk << 10) + hw;
        acc += sc[tk] * inv * V[krow * 256 + col];
    }
    O[qrow * 256 + col] = acc;
}

// ---------------- CLS frame (t=0): parallel reduce + broadcast --------------
__global__ void cls_reduce_kernel(const float* __restrict__ X, float* __restrict__ P)
{
    int chunk = blockIdx.x, b = blockIdx.y, d = threadIdx.x;
    long base = (long)(b * 9) * HWN * DIMN + (long)chunk * 128 * DIMN;
    float s = 0.f;
    #pragma unroll 4
    for (int hw = 0; hw < 128; hw++) s += X[base + (long)hw * DIMN + d];
    P[((long)b * 8 + chunk) * DIMN + d] = s;
}
__global__ void cls_bcast_kernel(const float* __restrict__ P, float* __restrict__ X)
{
    int chunk = blockIdx.x, b = blockIdx.y, d = threadIdx.x;
    float s = 0.f;
    #pragma unroll
    for (int c = 0; c < 8; c++) s += P[((long)b * 8 + c) * DIMN + d];
    s *= (1.f / 1024.f);
    long base = (long)(b * 9) * HWN * DIMN + (long)chunk * 128 * DIMN;
    #pragma unroll 4
    for (int hw = 0; hw < 128; hw++) X[base + (long)hw * DIMN + d] = s;
}

// ---------------- launch ----------------------------------------------------
extern "C" void kernel_launch(void* const* d_in, const int* in_sizes, int n_in,
                              void* d_out, int out_size)
{
    const float* query = (const float*)d_in[0];
    const unsigned char* tmask = (const unsigned char*)d_in[2];
    const float* sln_g = (const float*)d_in[3];
    const float* sln_b = (const float*)d_in[4];
    const float* s_wq = (const float*)d_in[5];  const float* s_bq = (const float*)d_in[6];
    const float* s_wk = (const float*)d_in[7];  const float* s_bk = (const float*)d_in[8];
    const float* s_wv = (const float*)d_in[9];  const float* s_bv = (const float*)d_in[10];
    const float* s_wo = (const float*)d_in[11]; const float* s_bo = (const float*)d_in[12];
    const float* tln_g = (const float*)d_in[13];
    const float* tln_b = (const float*)d_in[14];
    const float* t_wq = (const float*)d_in[15]; const float* t_bq = (const float*)d_in[16];
    const float* t_wk = (const float*)d_in[17]; const float* t_bk = (const float*)d_in[18];
    const float* t_wv = (const float*)d_in[19]; const float* t_bv = (const float*)d_in[20];
    const float* t_wo = (const float*)d_in[21]; const float* t_bo = (const float*)d_in[22];
    const float* mln_g = (const float*)d_in[23];
    const float* mln_b = (const float*)d_in[24];
    const float* w1 = (const float*)d_in[25];   const float* b1 = (const float*)d_in[26];
    const float* w2 = (const float*)d_in[27];   const float* b2 = (const float*)d_in[28];
    float* out = (float*)d_out;

    float *xn, *q, *k, *v, *o, *x, *h, *clsp;
    cudaGetSymbolAddress((void**)&xn, g_xn);
    cudaGetSymbolAddress((void**)&q,  g_q);
    cudaGetSymbolAddress((void**)&k,  g_k);
    cudaGetSymbolAddress((void**)&v,  g_v);
    cudaGetSymbolAddress((void**)&o,  g_o);
    cudaGetSymbolAddress((void**)&x,  g_x);
    cudaGetSymbolAddress((void**)&h,  g_h);
    cudaGetSymbolAddress((void**)&clsp, g_clsp);

    // ---- spatial block ----
    ln_kernel<<<NROWS_SP, 256>>>(query, sln_g, sln_b, xn, 1);
    gemm_kernel<<<dim3(2, NROWS_SP / 128), 256>>>(xn, s_wq, s_bq, nullptr, q, 256, 256, 0, 0);
    gemm_kernel<<<dim3(2, NROWS_SP / 128), 256>>>(xn, s_wk, s_bk, nullptr, k, 256, 256, 0, 0);
    gemm_kernel<<<dim3(2, NROWS_SP / 128), 256>>>(xn, s_wv, s_bv, nullptr, v, 256, 256, 0, 0);
    sattn_kernel<<<NROWS_SP, 256>>>(q, k, v, o);
    gemm_kernel<<<dim3(2, NROWS_SP / 128), 256>>>(o, s_wo, s_bo, query, x, 256, 256, 0, 1);
    copy8_kernel<<<4096, 256>>>(query, x);

    // ---- temporal block ----
    ln_kernel<<<NROWS, 256>>>(x, tln_g, tln_b, xn, 0);
    gemm_kernel<<<dim3(2, NROWS / 128), 256>>>(xn, t_wq, t_bq, nullptr, q, 256, 256, 0, 0);
    gemm_kernel<<<dim3(2, NROWS / 128), 256>>>(xn, t_wk, t_bk, nullptr, k, 256, 256, 0, 0);
    gemm_kernel<<<dim3(2, NROWS / 128), 256>>>(xn, t_wv, t_bv, nullptr, v, 256, 256, 0, 0);
    rope_kernel<<<(NROWS * 128) / 256, 256>>>(q, k);
    tattn_kernel<<<32768, 288>>>(q, k, v, tmask, o);
    gemm_kernel<<<dim3(2, NROWS / 128), 256>>>(o, t_wo, t_bo, x, x, 256, 1024 == 1024 ? 256 : 256, 0, 0);

    // ---- CLS average ----
    cls_reduce_kernel<<<dim3(8, 4), 256>>>(x, clsp);
    cls_bcast_kernel<<<dim3(8, 4), 256>>>(clsp, x);

    // ---- MLP ----
    ln_kernel<<<NROWS, 256>>>(x, mln_g, mln_b, xn, 0);
    gemm_kernel<<<dim3(8, NROWS / 128), 256>>>(xn, w1, b1, nullptr, h, 1024, 256, 1, 0);
    gemm_kernel<<<dim3(2, NROWS / 128), 256>>>(h, w2, b2, x, out, 256, 1024, 0, 0);
}

// round 7
// speedup vs baseline: 1.6924x; 1.4481x over previous
#include <cuda_runtime.h>
#include <cuda_bf16.h>
#include <math.h>
#include <stdint.h>

// Problem constants
#define BATCH 4
#define TQN   9
#define TFR   8
#define HWN   1024
#define DIMN  256
#define NHN   8
#define DHN   32
#define MLPD  1024
#define NROWS    (BATCH*TQN*HWN)   // 36864
#define NROWS_SP (BATCH*TFR*HWN)   // 32768
#define SCALE 0.17677669529663687f

// ---------------- scratch (static device memory; no allocations) -----------
__device__ __align__(16) float g_xn[NROWS*DIMN];
__device__ __align__(16) float g_q [NROWS*DIMN];
__device__ __align__(16) float g_k [NROWS*DIMN];
__device__ __align__(16) float g_v [NROWS*DIMN];
__device__ __align__(16) float g_o [NROWS*DIMN];
__device__ __align__(16) float g_x [NROWS*DIMN];
__device__ __align__(16) float g_h [(long)NROWS*MLPD];
__device__ __align__(16) float g_clsp[BATCH*8*DIMN];
// transposed + hi/lo-split weights (bf16): 8x 256*256 + 1024*256 + 256*1024
__device__ __align__(16) __nv_bfloat16 g_wth[1048576];
__device__ __align__(16) __nv_bfloat16 g_wtl[1048576];

// ---------------- helpers ----------------------------------------------
__device__ __forceinline__ uint32_t s2u(const void* p) {
    uint32_t a;
    asm("{ .reg .u64 t; cvta.to.shared.u64 t, %1; cvt.u32.u64 %0, t; }" : "=r"(a) : "l"(p));
    return a;
}
__device__ __forceinline__ void ldsm4(uint32_t* r, uint32_t addr) {
    asm volatile("ldmatrix.sync.aligned.m8n8.x4.shared.b16 {%0,%1,%2,%3}, [%4];"
                 : "=r"(r[0]), "=r"(r[1]), "=r"(r[2]), "=r"(r[3]) : "r"(addr));
}
__device__ __forceinline__ void mma16816(float* d, const uint32_t* a, const uint32_t* b) {
    asm volatile("mma.sync.aligned.m16n8k16.row.col.f32.bf16.bf16.f32 "
                 "{%0,%1,%2,%3}, {%4,%5,%6,%7}, {%8,%9}, {%0,%1,%2,%3};"
                 : "+f"(d[0]), "+f"(d[1]), "+f"(d[2]), "+f"(d[3])
                 : "r"(a[0]), "r"(a[1]), "r"(a[2]), "r"(a[3]), "r"(b[0]), "r"(b[1]));
}

// ---------------- weight transpose + hi/lo split ----------------------------
// W: [K, M] fp32 -> Th/Tl: [M, K] bf16
__global__ void wsplit_kernel(const float* __restrict__ W, __nv_bfloat16* __restrict__ Th,
                              __nv_bfloat16* __restrict__ Tl, int K, int M)
{
    __shared__ float tile[32][33];
    int mb = blockIdx.x * 32, kb = blockIdx.y * 32;
    int tx = threadIdx.x, ty = threadIdx.y;
    #pragma unroll
    for (int i = 0; i < 32; i += 8)
        tile[ty + i][tx] = W[(long)(kb + ty + i) * M + mb + tx];
    __syncthreads();
    #pragma unroll
    for (int i = 0; i < 32; i += 8) {
        float v = tile[tx][ty + i];
        __nv_bfloat16 h = __float2bfloat16(v);
        __nv_bfloat16 l = __float2bfloat16(v - __bfloat162float(h));
        long o = (long)(mb + ty + i) * K + kb + tx;
        Th[o] = h; Tl[o] = l;
    }
}

// ---------------- mma.sync bf16 split-precision GEMM ------------------------
// C[rows, M] = A[rows, K] @ Wt^T (Wt: [M, K] bf16 hi/lo) + bias (+gelu)(+res)
// 128x128 tile, BK=64 chunks, 8 warps (2m x 4n), warp tile 64x32.
// D = Ah*Bh + Ah*Bl + Al*Bh (fp32 accum) — rel err ~2^-16.
#define AH_OFF 0
#define AL_OFF 16384
#define BH_OFF 32768
#define BL_OFF 49152
#define MMA_SMEM 65536

__global__ void __launch_bounds__(256)
mmagemm(const float* __restrict__ A, const __nv_bfloat16* __restrict__ Wh,
        const __nv_bfloat16* __restrict__ Wl, const float* __restrict__ bias,
        const float* __restrict__ res, float* __restrict__ out,
        int M, int K, int act, int remap)
{
    extern __shared__ __align__(1024) char smem[];
    uint32_t sb = s2u(smem);
    int tid = threadIdx.x, wid = tid >> 5, lane = tid & 31;
    int wm = (wid & 1) * 64;      // warp m offset
    int wn = (wid >> 1) * 32;     // warp n offset

    long rowBase = (long)blockIdx.y * 128;
    int  colBase = blockIdx.x * 128;
    const float* Ap = A + rowBase * K;
    const __nv_bfloat16* Whp = Wh + (long)colBase * K;
    const __nv_bfloat16* Wlp = Wl + (long)colBase * K;

    float acc[4][4][4];
    #pragma unroll
    for (int i = 0; i < 4; i++)
        #pragma unroll
        for (int j = 0; j < 4; j++)
            #pragma unroll
            for (int t = 0; t < 4; t++) acc[i][j][t] = 0.f;

    int nchunk = K >> 6;
    for (int c = 0; c < nchunk; c++) {
        int kbase = c << 6;
        // ---- stage A chunk: fp32 -> split bf16, SW128 swizzled [128][64] ----
        #pragma unroll
        for (int i = 0; i < 16; i++) {
            int p = tid + i * 256;            // 0..4095 float2 slots
            int row = p >> 5;
            int kp = (p & 31) * 2;
            float2 v = *(const float2*)&Ap[(long)row * K + kbase + kp];
            __nv_bfloat16 h0 = __float2bfloat16(v.x), h1 = __float2bfloat16(v.y);
            float r0 = v.x - __bfloat162float(h0), r1 = v.y - __bfloat162float(h1);
            __nv_bfloat16 l0 = __float2bfloat16(r0), l1 = __float2bfloat16(r1);
            uint32_t hw_ = ((uint32_t)__bfloat16_as_ushort(h1) << 16) | __bfloat16_as_ushort(h0);
            uint32_t lw_ = ((uint32_t)__bfloat16_as_ushort(l1) << 16) | __bfloat16_as_ushort(l0);
            uint32_t off = row * 128 + kp * 2;
            uint32_t sw = off ^ ((off >> 3) & 0x70);
            *(uint32_t*)(smem + AH_OFF + sw) = hw_;
            *(uint32_t*)(smem + AL_OFF + sw) = lw_;
        }
        // ---- stage B chunk: pre-split bf16, swizzled copy [128][64] ----
        #pragma unroll
        for (int i = 0; i < 16; i++) {
            int p = tid + i * 256;
            int row = p >> 5;
            int kp = (p & 31) * 2;
            uint32_t hv = *(const uint32_t*)&Whp[(long)row * K + kbase + kp];
            uint32_t lv = *(const uint32_t*)&Wlp[(long)row * K + kbase + kp];
            uint32_t off = row * 128 + kp * 2;
            uint32_t sw = off ^ ((off >> 3) & 0x70);
            *(uint32_t*)(smem + BH_OFF + sw) = hv;
            *(uint32_t*)(smem + BL_OFF + sw) = lv;
        }
        __syncthreads();

        // ---- mma over 4 k-slices of 16 ----
        #pragma unroll
        for (int ks = 0; ks < 4; ks++) {
            uint32_t ah[4][4], al[4][4];
            #pragma unroll
            for (int ma = 0; ma < 4; ma++) {
                int row = wm + ma * 16 + (lane & 15);
                int ch  = ks * 2 + (lane >> 4);
                uint32_t off = row * 128 + ch * 16;
                uint32_t sw = off ^ ((off >> 3) & 0x70);
                ldsm4(ah[ma], sb + AH_OFF + sw);
                ldsm4(al[ma], sb + AL_OFF + sw);
            }
            uint32_t bh[2][4], bl[2][4];
            #pragma unroll
            for (int np = 0; np < 2; np++) {
                int g = lane >> 3;
                int nrow = wn + np * 16 + (g >> 1) * 8 + (lane & 7);
                int ch = ks * 2 + (g & 1);
                uint32_t off = nrow * 128 + ch * 16;
                uint32_t sw = off ^ ((off >> 3) & 0x70);
                ldsm4(bh[np], sb + BH_OFF + sw);
                ldsm4(bl[np], sb + BL_OFF + sw);
            }
            #pragma unroll
            for (int ma = 0; ma < 4; ma++)
                #pragma unroll
                for (int na = 0; na < 4; na++) {
                    const uint32_t* bhp = &bh[na >> 1][(na & 1) * 2];
                    const uint32_t* blp = &bl[na >> 1][(na & 1) * 2];
                    mma16816(acc[ma][na], ah[ma], bhp);
                    mma16816(acc[ma][na], ah[ma], blp);
                    mma16816(acc[ma][na], al[ma], bhp);
                }
        }
        __syncthreads();
    }

    // ---- epilogue ----
    #pragma unroll
    for (int ma = 0; ma < 4; ma++) {
        #pragma unroll
        for (int half = 0; half < 2; half++) {
            long m = rowBase + wm + ma * 16 + (lane >> 2) + half * 8;
            long om = m;
            if (remap) { int b = (int)(m >> 13), t = (int)((m >> 10) & 7), hw = (int)(m & 1023);
                         om = ((long)(b * 9 + t) << 10) + hw; }
            #pragma unroll
            for (int na = 0; na < 4; na++) {
                int n0 = colBase + wn + na * 8 + (lane & 3) * 2;
                float2 bv = *(const float2*)&bias[n0];
                float2 vv;
                vv.x = acc[ma][na][half * 2 + 0] + bv.x;
                vv.y = acc[ma][na][half * 2 + 1] + bv.y;
                if (act == 1) {
                    vv.x = 0.5f * vv.x * (1.f + erff(vv.x * 0.70710678118654752f));
                    vv.y = 0.5f * vv.y * (1.f + erff(vv.y * 0.70710678118654752f));
                }
                if (res) {
                    float2 rv = *(const float2*)&res[om * M + n0];
                    vv.x += rv.x; vv.y += rv.y;
                }
                *(float2*)&out[om * M + n0] = vv;
            }
        }
    }
}

// ---------------- LayerNorm: one block (256 thr) per row --------------------
__global__ void ln_kernel(const float* __restrict__ in, const float* __restrict__ g,
                          const float* __restrict__ bta, float* __restrict__ out, int remap)
{
    int r = blockIdx.x;
    long ir = r;
    if (remap) { int b = r >> 13, t = (r >> 10) & 7, hw = r & 1023;
                 ir = ((long)(b * 9 + t) << 10) + hw; }
    float v = in[ir * DIMN + threadIdx.x];
    __shared__ float sbuf[40];
    float s = v, q = v * v;
    #pragma unroll
    for (int o = 16; o; o >>= 1) { s += __shfl_xor_sync(~0u, s, o); q += __shfl_xor_sync(~0u, q, o); }
    int w = threadIdx.x >> 5;
    if ((threadIdx.x & 31) == 0) { sbuf[w] = s; sbuf[8 + w] = q; }
    __syncthreads();
    if (threadIdx.x < 32) {
        s = (threadIdx.x < 8) ? sbuf[threadIdx.x] : 0.f;
        q = (threadIdx.x < 8) ? sbuf[8 + threadIdx.x] : 0.f;
        #pragma unroll
        for (int o = 4; o; o >>= 1) { s += __shfl_xor_sync(~0u, s, o); q += __shfl_xor_sync(~0u, q, o); }
        if (threadIdx.x == 0) { sbuf[32] = s; sbuf[33] = q; }
    }
    __syncthreads();
    float mean = sbuf[32] * (1.f / 256.f);
    float var  = sbuf[33] * (1.f / 256.f) - mean * mean;
    out[(long)r * DIMN + threadIdx.x] =
        (v - mean) * rsqrtf(var + 1e-5f) * g[threadIdx.x] + bta[threadIdx.x];
}

// ---------------- Spatial windowed attention (9 neighbors) ------------------
__global__ void sattn_kernel(const float* __restrict__ Q, const float* __restrict__ K,
                             const float* __restrict__ V, float* __restrict__ O)
{
    int r = blockIdx.x;
    int bt = r >> 10, pix = r & 1023;
    int y = pix >> 5, x = pix & 31;
    int c = threadIdx.x;
    float qv = Q[(long)r * 256 + c];
    float sc[9];
    #pragma unroll
    for (int n = 0; n < 9; n++) {
        int dy = n / 3 - 1, dx = n % 3 - 1;
        int ny = y + dy, nx = x + dx;
        bool ok = ((unsigned)ny < 32u) && ((unsigned)nx < 32u);
        float p = 0.f;
        if (ok) p = qv * K[(((long)(bt << 10) + (ny << 5) + nx) << 8) + c];
        #pragma unroll
        for (int o = 16; o; o >>= 1) p += __shfl_xor_sync(~0u, p, o);
        sc[n] = ok ? p * SCALE : -1e9f;
    }
    float mx = sc[0];
    #pragma unroll
    for (int n = 1; n < 9; n++) mx = fmaxf(mx, sc[n]);
    float den = 0.f;
    #pragma unroll
    for (int n = 0; n < 9; n++) { sc[n] = expf(sc[n] - mx); den += sc[n]; }
    float inv = 1.f / den;
    float acc = 0.f;
    #pragma unroll
    for (int n = 0; n < 9; n++) {
        int dy = n / 3 - 1, dx = n % 3 - 1;
        int ny = y + dy, nx = x + dx;
        if (((unsigned)ny < 32u) && ((unsigned)nx < 32u))
            acc += sc[n] * inv * V[(((long)(bt << 10) + (ny << 5) + nx) << 8) + c];
    }
    O[(long)r * 256 + c] = acc;
}

// ---------------- copy CLS/last frame (t=8) query -> X ----------------------
__global__ void copy8_kernel(const float* __restrict__ q, float* __restrict__ X)
{
    long idx = (long)blockIdx.x * 256 + threadIdx.x;
    int b = (int)(idx >> 18);
    long rem = idx & 262143;
    long off = ((long)(b * 9 + 8)) * 262144 + rem;
    X[off] = q[off];
}

// ---------------- RoPE in-place on temporal q,k -----------------------------
__global__ void rope_kernel(float* __restrict__ Q, float* __restrict__ K)
{
    long idx = (long)blockIdx.x * 256 + threadIdx.x;
    long row = idx >> 7;
    int pr = (int)(idx & 127);
    int h = pr >> 4, i = pr & 15;
    int t = (int)((row >> 10) % 9);
    float invf = exp2f(-(float)i * 0.83048202372184058696f);
    float ang = (float)t * invf;
    float cs, sn;
    sincosf(ang, &sn, &cs);
    long o1 = row * 256 + h * 32 + i, o2 = o1 + 16;
    float q1 = Q[o1], q2 = Q[o2];
    Q[o1] = q1 * cs - q2 * sn;  Q[o2] = q1 * sn + q2 * cs;
    float k1 = K[o1], k2 = K[o2];
    K[o1] = k1 * cs - k2 * sn;  K[o2] = k1 * sn + k2 * cs;
}

// ---------------- Temporal attention: block=(b,hw,h), warp=tq ---------------
__global__ void tattn_kernel(const float* __restrict__ Q, const float* __restrict__ K,
                             const float* __restrict__ V, const unsigned char* __restrict__ mask,
                             float* __restrict__ O)
{
    int blk = blockIdx.x;
    int h = blk & 7, hw = (blk >> 3) & 1023, b = blk >> 13;
    int tq = threadIdx.x >> 5, lane = threadIdx.x & 31;
    int col = (h << 5) + lane;
    long base = ((long)b * TQN) << 10;
    long qrow = base + ((long)tq << 10) + hw;
    float qv = Q[qrow * 256 + col];
    float sc[9];
    #pragma unroll
    for (int tk = 0; tk < 9; tk++) {
        long krow = base + ((long)tk << 10) + hw;
        float p = qv * K[krow * 256 + col];
        #pragma unroll
        for (int o = 16; o; o >>= 1) p += __shfl_xor_sync(~0u, p, o);
        sc[tk] = mask[tq * 9 + tk] ? -1e9f : p * SCALE;
    }
    float mx = sc[0];
    #pragma unroll
    for (int i = 1; i < 9; i++) mx = fmaxf(mx, sc[i]);
    float den = 0.f;
    #pragma unroll
    for (int i = 0; i < 9; i++) { sc[i] = expf(sc[i] - mx); den += sc[i]; }
    float inv = 1.f / den;
    float acc = 0.f;
    #pragma unroll
    for (int tk = 0; tk < 9; tk++) {
        long krow = base + ((long)tk << 10) + hw;
        acc += sc[tk] * inv * V[krow * 256 + col];
    }
    O[qrow * 256 + col] = acc;
}

// ---------------- CLS frame (t=0): parallel reduce + broadcast --------------
__global__ void cls_reduce_kernel(const float* __restrict__ X, float* __restrict__ P)
{
    int chunk = blockIdx.x, b = blockIdx.y, d = threadIdx.x;
    long base = (long)(b * 9) * HWN * DIMN + (long)chunk * 128 * DIMN;
    float s = 0.f;
    #pragma unroll 4
    for (int hw = 0; hw < 128; hw++) s += X[base + (long)hw * DIMN + d];
    P[((long)b * 8 + chunk) * DIMN + d] = s;
}
__global__ void cls_bcast_kernel(const float* __restrict__ P, float* __restrict__ X)
{
    int chunk = blockIdx.x, b = blockIdx.y, d = threadIdx.x;
    float s = 0.f;
    #pragma unroll
    for (int c = 0; c < 8; c++) s += P[((long)b * 8 + c) * DIMN + d];
    s *= (1.f / 1024.f);
    long base = (long)(b * 9) * HWN * DIMN + (long)chunk * 128 * DIMN;
    #pragma unroll 4
    for (int hw = 0; hw < 128; hw++) X[base + (long)hw * DIMN + d] = s;
}

// ---------------- launch ----------------------------------------------------
#define O_SWQ 0
#define O_SWK 65536
#define O_SWV 131072
#define O_SWO 196608
#define O_TWQ 262144
#define O_TWK 327680
#define O_TWV 393216
#define O_TWO 458752
#define O_W1  524288
#define O_W2  786432

extern "C" void kernel_launch(void* const* d_in, const int* in_sizes, int n_in,
                              void* d_out, int out_size)
{
    const float* query = (const float*)d_in[0];
    const unsigned char* tmask = (const unsigned char*)d_in[2];
    const float* sln_g = (const float*)d_in[3];
    const float* sln_b = (const float*)d_in[4];
    const float* s_wq = (const float*)d_in[5];  const float* s_bq = (const float*)d_in[6];
    const float* s_wk = (const float*)d_in[7];  const float* s_bk = (const float*)d_in[8];
    const float* s_wv = (const float*)d_in[9];  const float* s_bv = (const float*)d_in[10];
    const float* s_wo = (const float*)d_in[11]; const float* s_bo = (const float*)d_in[12];
    const float* tln_g = (const float*)d_in[13];
    const float* tln_b = (const float*)d_in[14];
    const float* t_wq = (const float*)d_in[15]; const float* t_bq = (const float*)d_in[16];
    const float* t_wk = (const float*)d_in[17]; const float* t_bk = (const float*)d_in[18];
    const float* t_wv = (const float*)d_in[19]; const float* t_bv = (const float*)d_in[20];
    const float* t_wo = (const float*)d_in[21]; const float* t_bo = (const float*)d_in[22];
    const float* mln_g = (const float*)d_in[23];
    const float* mln_b = (const float*)d_in[24];
    const float* w1 = (const float*)d_in[25];   const float* b1 = (const float*)d_in[26];
    const float* w2 = (const float*)d_in[27];   const float* b2 = (const float*)d_in[28];
    float* out = (float*)d_out;

    float *xn, *q, *k, *v, *o, *x, *h, *clsp;
    __nv_bfloat16 *wth, *wtl;
    cudaGetSymbolAddress((void**)&xn, g_xn);
    cudaGetSymbolAddress((void**)&q,  g_q);
    cudaGetSymbolAddress((void**)&k,  g_k);
    cudaGetSymbolAddress((void**)&v,  g_v);
    cudaGetSymbolAddress((void**)&o,  g_o);
    cudaGetSymbolAddress((void**)&x,  g_x);
    cudaGetSymbolAddress((void**)&h,  g_h);
    cudaGetSymbolAddress((void**)&clsp, g_clsp);
    cudaGetSymbolAddress((void**)&wth, g_wth);
    cudaGetSymbolAddress((void**)&wtl, g_wtl);

    cudaFuncSetAttribute(mmagemm, cudaFuncAttributeMaxDynamicSharedMemorySize, MMA_SMEM);

    // ---- weight transpose + split ----
    dim3 tb(32, 8);
    wsplit_kernel<<<dim3(8, 8),  tb>>>(s_wq, wth + O_SWQ, wtl + O_SWQ, 256, 256);
    wsplit_kernel<<<dim3(8, 8),  tb>>>(s_wk, wth + O_SWK, wtl + O_SWK, 256, 256);
    wsplit_kernel<<<dim3(8, 8),  tb>>>(s_wv, wth + O_SWV, wtl + O_SWV, 256, 256);
    wsplit_kernel<<<dim3(8, 8),  tb>>>(s_wo, wth + O_SWO, wtl + O_SWO, 256, 256);
    wsplit_kernel<<<dim3(8, 8),  tb>>>(t_wq, wth + O_TWQ, wtl + O_TWQ, 256, 256);
    wsplit_kernel<<<dim3(8, 8),  tb>>>(t_wk, wth + O_TWK, wtl + O_TWK, 256, 256);
    wsplit_kernel<<<dim3(8, 8),  tb>>>(t_wv, wth + O_TWV, wtl + O_TWV, 256, 256);
    wsplit_kernel<<<dim3(8, 8),  tb>>>(t_wo, wth + O_TWO, wtl + O_TWO, 256, 256);
    wsplit_kernel<<<dim3(32, 8), tb>>>(w1,   wth + O_W1,  wtl + O_W1,  256, 1024);
    wsplit_kernel<<<dim3(8, 32), tb>>>(w2,   wth + O_W2,  wtl + O_W2,  1024, 256);

    // ---- spatial block ----
    ln_kernel<<<NROWS_SP, 256>>>(query, sln_g, sln_b, xn, 1);
    mmagemm<<<dim3(2, NROWS_SP/128), 256, MMA_SMEM>>>(xn, wth+O_SWQ, wtl+O_SWQ, s_bq, nullptr, q, 256, 256, 0, 0);
    mmagemm<<<dim3(2, NROWS_SP/128), 256, MMA_SMEM>>>(xn, wth+O_SWK, wtl+O_SWK, s_bk, nullptr, k, 256, 256, 0, 0);
    mmagemm<<<dim3(2, NROWS_SP/128), 256, MMA_SMEM>>>(xn, wth+O_SWV, wtl+O_SWV, s_bv, nullptr, v, 256, 256, 0, 0);
    sattn_kernel<<<NROWS_SP, 256>>>(q, k, v, o);
    mmagemm<<<dim3(2, NROWS_SP/128), 256, MMA_SMEM>>>(o, wth+O_SWO, wtl+O_SWO, s_bo, query, x, 256, 256, 0, 1);
    copy8_kernel<<<4096, 256>>>(query, x);

    // ---- temporal block ----
    ln_kernel<<<NROWS, 256>>>(x, tln_g, tln_b, xn, 0);
    mmagemm<<<dim3(2, NROWS/128), 256, MMA_SMEM>>>(xn, wth+O_TWQ, wtl+O_TWQ, t_bq, nullptr, q, 256, 256, 0, 0);
    mmagemm<<<dim3(2, NROWS/128), 256, MMA_SMEM>>>(xn, wth+O_TWK, wtl+O_TWK, t_bk, nullptr, k, 256, 256, 0, 0);
    mmagemm<<<dim3(2, NROWS/128), 256, MMA_SMEM>>>(xn, wth+O_TWV, wtl+O_TWV, t_bv, nullptr, v, 256, 256, 0, 0);
    rope_kernel<<<(NROWS * 128) / 256, 256>>>(q, k);
    tattn_kernel<<<32768, 288>>>(q, k, v, tmask, o);
    mmagemm<<<dim3(2, NROWS/128), 256, MMA_SMEM>>>(o, wth+O_TWO, wtl+O_TWO, t_bo, x, x, 256, 256, 0, 0);

    // ---- CLS average ----
    cls_reduce_kernel<<<dim3(8, 4), 256>>>(x, clsp);
    cls_bcast_kernel<<<dim3(8, 4), 256>>>(clsp, x);

    // ---- MLP ----
    ln_kernel<<<NROWS, 256>>>(x, mln_g, mln_b, xn, 0);
    mmagemm<<<dim3(8, NROWS/128), 256, MMA_SMEM>>>(xn, wth+O_W1, wtl+O_W1, b1, nullptr, h, 1024, 256, 1, 0);
    mmagemm<<<dim3(2, NROWS/128), 256, MMA_SMEM>>>(h,  wth+O_W2, wtl+O_W2, b2, x, out, 256, 1024, 0, 0);
}

// round 8
// speedup vs baseline: 1.8613x; 1.0998x over previous
#include <cuda_runtime.h>
#include <cuda_bf16.h>
#include <math.h>
#include <stdint.h>

// Problem constants
#define BATCH 4
#define TQN   9
#define TFR   8
#define HWN   1024
#define DIMN  256
#define NHN   8
#define DHN   32
#define MLPD  1024
#define NROWS    (BATCH*TQN*HWN)   // 36864
#define NROWS_SP (BATCH*TFR*HWN)   // 32768
#define SCALE 0.17677669529663687f

// ---------------- scratch (static device memory; no allocations) -----------
__device__ __align__(16) float g_q [NROWS*DIMN];
__device__ __align__(16) float g_k [NROWS*DIMN];
__device__ __align__(16) float g_v [NROWS*DIMN];
__device__ __align__(16) float g_x [NROWS*DIMN];
__device__ __align__(16) float g_clsp[BATCH*8*DIMN];
// split activations (bf16 hi/lo)
__device__ __align__(16) __nv_bfloat16 g_xnh[NROWS*DIMN];
__device__ __align__(16) __nv_bfloat16 g_xnl[NROWS*DIMN];
__device__ __align__(16) __nv_bfloat16 g_oh [NROWS*DIMN];
__device__ __align__(16) __nv_bfloat16 g_ol [NROWS*DIMN];
__device__ __align__(16) __nv_bfloat16 g_hh [(long)NROWS*MLPD];
__device__ __align__(16) __nv_bfloat16 g_hl [(long)NROWS*MLPD];
// transposed + hi/lo-split weights
__device__ __align__(16) __nv_bfloat16 g_wth[1048576];
__device__ __align__(16) __nv_bfloat16 g_wtl[1048576];

// ---------------- helpers ----------------------------------------------
__device__ __forceinline__ uint32_t s2u(const void* p) {
    uint32_t a;
    asm("{ .reg .u64 t; cvta.to.shared.u64 t, %1; cvt.u32.u64 %0, t; }" : "=r"(a) : "l"(p));
    return a;
}
__device__ __forceinline__ void ldsm4(uint32_t* r, uint32_t addr) {
    asm volatile("ldmatrix.sync.aligned.m8n8.x4.shared.b16 {%0,%1,%2,%3}, [%4];"
                 : "=r"(r[0]), "=r"(r[1]), "=r"(r[2]), "=r"(r[3]) : "r"(addr));
}
__device__ __forceinline__ void mma16816(float* d, const uint32_t* a, const uint32_t* b) {
    asm volatile("mma.sync.aligned.m16n8k16.row.col.f32.bf16.bf16.f32 "
                 "{%0,%1,%2,%3}, {%4,%5,%6,%7}, {%8,%9}, {%0,%1,%2,%3};"
                 : "+f"(d[0]), "+f"(d[1]), "+f"(d[2]), "+f"(d[3])
                 : "r"(a[0]), "r"(a[1]), "r"(a[2]), "r"(a[3]), "r"(b[0]), "r"(b[1]));
}
__device__ __forceinline__ void cpa16(uint32_t sm, const void* g) {
    asm volatile("cp.async.cg.shared.global [%0], [%1], 16;" :: "r"(sm), "l"(g));
}
__device__ __forceinline__ void split_bf16(float v, __nv_bfloat16& h, __nv_bfloat16& l) {
    h = __float2bfloat16(v);
    l = __float2bfloat16(v - __bfloat162float(h));
}

// ---------------- all-weights transpose + hi/lo split (one launch) ----------
// jobs 0..7: 256x256 mats; job 8: w1 [256,1024]; job 9: w2 [1024,256]
__global__ void wsplit_all(const float* s0, const float* s1, const float* s2, const float* s3,
                           const float* s4, const float* s5, const float* s6, const float* s7,
                           const float* s8, const float* s9,
                           __nv_bfloat16* __restrict__ Th, __nv_bfloat16* __restrict__ Tl)
{
    __shared__ float tile[32][33];
    int t = blockIdx.x;
    const float* W; long dst; int K, M, mtile, ktile;
    if (t < 512) {
        int j = t >> 6, wi = t & 63;
        K = 256; M = 256; mtile = wi & 7; ktile = wi >> 3;
        dst = (long)j * 65536;
        switch (j) {
            case 0: W = s0; break; case 1: W = s1; break; case 2: W = s2; break;
            case 3: W = s3; break; case 4: W = s4; break; case 5: W = s5; break;
            case 6: W = s6; break; default: W = s7; break;
        }
    } else if (t < 768) {
        int wi = t - 512;
        K = 256; M = 1024; mtile = wi & 31; ktile = wi >> 5;
        dst = 524288; W = s8;
    } else {
        int wi = t - 768;
        K = 1024; M = 256; mtile = wi & 7; ktile = wi >> 3;
        dst = 786432; W = s9;
    }
    int mb = mtile * 32, kb = ktile * 32;
    int tx = threadIdx.x, ty = threadIdx.y;
    #pragma unroll
    for (int i = 0; i < 32; i += 8)
        tile[ty + i][tx] = W[(long)(kb + ty + i) * M + mb + tx];
    __syncthreads();
    #pragma unroll
    for (int i = 0; i < 32; i += 8) {
        float v = tile[tx][ty + i];
        __nv_bfloat16 h, l; split_bf16(v, h, l);
        long o = dst + (long)(mb + ty + i) * K + kb + tx;
        Th[o] = h; Tl[o] = l;
    }
}

// ---------------- mma.sync bf16 split-precision GEMM ------------------------
// C[rows, M] = (Ah+Al)[rows,K] @ (Wh+Wl)^T + bias; D = Ah*Bh + Ah*Bl + Al*Bh.
// act==0: out fp32 (+res). act==1: gelu then split-bf16 -> outh/outl.
#define AH_OFF 0
#define AL_OFF 16384
#define BH_OFF 32768
#define BL_OFF 49152
#define MMA_SMEM 65536

__global__ void __launch_bounds__(256)
mmagemm(const __nv_bfloat16* __restrict__ Ah, const __nv_bfloat16* __restrict__ Al,
        const __nv_bfloat16* __restrict__ Wh, const __nv_bfloat16* __restrict__ Wl,
        const float* __restrict__ bias, const float* __restrict__ res,
        float* __restrict__ out, __nv_bfloat16* __restrict__ outh,
        __nv_bfloat16* __restrict__ outl, int M, int K, int act, int remap)
{
    extern __shared__ __align__(1024) char smem[];
    uint32_t sb = s2u(smem);
    int tid = threadIdx.x, wid = tid >> 5, lane = tid & 31;
    int wm = (wid & 1) * 64, wn = (wid >> 1) * 32;

    long rowBase = (long)blockIdx.y * 128;
    int  colBase = blockIdx.x * 128;
    const __nv_bfloat16* Ahp = Ah + rowBase * K;
    const __nv_bfloat16* Alp = Al + rowBase * K;
    const __nv_bfloat16* Whp = Wh + (long)colBase * K;
    const __nv_bfloat16* Wlp = Wl + (long)colBase * K;

    float acc[4][4][4];
    #pragma unroll
    for (int i = 0; i < 4; i++)
        #pragma unroll
        for (int j = 0; j < 4; j++)
            #pragma unroll
            for (int tt = 0; tt < 4; tt++) acc[i][j][tt] = 0.f;

    int nchunk = K >> 6;
    for (int c = 0; c < nchunk; c++) {
        int kbase = c << 6;
        // stage: pure 16B async copies, SW128 swizzled [128 rows][64 cols bf16]
        #pragma unroll
        for (int i = 0; i < 4; i++) {
            int s = tid + i * 256;            // 0..1023 16B slots per buffer
            int row = s >> 3;
            int kb = (s & 7) * 8;             // bf16 col offset
            uint32_t off = row * 128 + kb * 2;
            uint32_t sw = off ^ ((off >> 3) & 0x70);
            long go = (long)row * K + kbase + kb;
            cpa16(sb + AH_OFF + sw, Ahp + go);
            cpa16(sb + AL_OFF + sw, Alp + go);
            cpa16(sb + BH_OFF + sw, Whp + go);
            cpa16(sb + BL_OFF + sw, Wlp + go);
        }
        asm volatile("cp.async.commit_group;");
        asm volatile("cp.async.wait_group 0;" ::: "memory");
        __syncthreads();

        #pragma unroll
        for (int ks = 0; ks < 4; ks++) {
            uint32_t ah[4][4], al[4][4];
            #pragma unroll
            for (int ma = 0; ma < 4; ma++) {
                int row = wm + ma * 16 + (lane & 15);
                int ch  = ks * 2 + (lane >> 4);
                uint32_t off = row * 128 + ch * 16;
                uint32_t sw = off ^ ((off >> 3) & 0x70);
                ldsm4(ah[ma], sb + AH_OFF + sw);
                ldsm4(al[ma], sb + AL_OFF + sw);
            }
            uint32_t bh[2][4], bl[2][4];
            #pragma unroll
            for (int np = 0; np < 2; np++) {
                int g = lane >> 3;
                int nrow = wn + np * 16 + (g >> 1) * 8 + (lane & 7);
                int ch = ks * 2 + (g & 1);
                uint32_t off = nrow * 128 + ch * 16;
                uint32_t sw = off ^ ((off >> 3) & 0x70);
                ldsm4(bh[np], sb + BH_OFF + sw);
                ldsm4(bl[np], sb + BL_OFF + sw);
            }
            #pragma unroll
            for (int ma = 0; ma < 4; ma++)
                #pragma unroll
                for (int na = 0; na < 4; na++) {
                    const uint32_t* bhp = &bh[na >> 1][(na & 1) * 2];
                    const uint32_t* blp = &bl[na >> 1][(na & 1) * 2];
                    mma16816(acc[ma][na], ah[ma], bhp);
                    mma16816(acc[ma][na], ah[ma], blp);
                    mma16816(acc[ma][na], al[ma], bhp);
                }
        }
        __syncthreads();
    }

    // ---- epilogue ----
    #pragma unroll
    for (int ma = 0; ma < 4; ma++) {
        #pragma unroll
        for (int half = 0; half < 2; half++) {
            long m = rowBase + wm + ma * 16 + (lane >> 2) + half * 8;
            long om = m;
            if (remap) { int b = (int)(m >> 13), t = (int)((m >> 10) & 7), hw = (int)(m & 1023);
                         om = ((long)(b * 9 + t) << 10) + hw; }
            #pragma unroll
            for (int na = 0; na < 4; na++) {
                int n0 = colBase + wn + na * 8 + (lane & 3) * 2;
                float2 bv = *(const float2*)&bias[n0];
                float2 vv;
                vv.x = acc[ma][na][half * 2 + 0] + bv.x;
                vv.y = acc[ma][na][half * 2 + 1] + bv.y;
                if (act == 1) {
                    vv.x = 0.5f * vv.x * (1.f + erff(vv.x * 0.70710678118654752f));
                    vv.y = 0.5f * vv.y * (1.f + erff(vv.y * 0.70710678118654752f));
                    __nv_bfloat16 hx, lx, hy, ly;
                    split_bf16(vv.x, hx, lx);
                    split_bf16(vv.y, hy, ly);
                    uint32_t hw_ = ((uint32_t)__bfloat16_as_ushort(hy) << 16) | __bfloat16_as_ushort(hx);
                    uint32_t lw_ = ((uint32_t)__bfloat16_as_ushort(ly) << 16) | __bfloat16_as_ushort(lx);
                    *(uint32_t*)&outh[om * M + n0] = hw_;
                    *(uint32_t*)&outl[om * M + n0] = lw_;
                } else {
                    if (res) {
                        float2 rv = *(const float2*)&res[om * M + n0];
                        vv.x += rv.x; vv.y += rv.y;
                    }
                    *(float2*)&out[om * M + n0] = vv;
                }
            }
        }
    }
}

// ---------------- LayerNorm -> split bf16 -----------------------------------
__global__ void ln_kernel(const float* __restrict__ in, const float* __restrict__ g,
                          const float* __restrict__ bta, __nv_bfloat16* __restrict__ outh,
                          __nv_bfloat16* __restrict__ outl, int remap)
{
    int r = blockIdx.x;
    long ir = r;
    if (remap) { int b = r >> 13, t = (r >> 10) & 7, hw = r & 1023;
                 ir = ((long)(b * 9 + t) << 10) + hw; }
    float v = in[ir * DIMN + threadIdx.x];
    __shared__ float sbuf[40];
    float s = v, q = v * v;
    #pragma unroll
    for (int o = 16; o; o >>= 1) { s += __shfl_xor_sync(~0u, s, o); q += __shfl_xor_sync(~0u, q, o); }
    int w = threadIdx.x >> 5;
    if ((threadIdx.x & 31) == 0) { sbuf[w] = s; sbuf[8 + w] = q; }
    __syncthreads();
    if (threadIdx.x < 32) {
        s = (threadIdx.x < 8) ? sbuf[threadIdx.x] : 0.f;
        q = (threadIdx.x < 8) ? sbuf[8 + threadIdx.x] : 0.f;
        #pragma unroll
        for (int o = 4; o; o >>= 1) { s += __shfl_xor_sync(~0u, s, o); q += __shfl_xor_sync(~0u, q, o); }
        if (threadIdx.x == 0) { sbuf[32] = s; sbuf[33] = q; }
    }
    __syncthreads();
    float mean = sbuf[32] * (1.f / 256.f);
    float var  = sbuf[33] * (1.f / 256.f) - mean * mean;
    float vo = (v - mean) * rsqrtf(var + 1e-5f) * g[threadIdx.x] + bta[threadIdx.x];
    __nv_bfloat16 h, l; split_bf16(vo, h, l);
    outh[(long)r * DIMN + threadIdx.x] = h;
    outl[(long)r * DIMN + threadIdx.x] = l;
}

// ---------------- Spatial windowed attention -> split bf16 ------------------
__global__ void sattn_kernel(const float* __restrict__ Q, const float* __restrict__ K,
                             const float* __restrict__ V,
                             __nv_bfloat16* __restrict__ Oh, __nv_bfloat16* __restrict__ Ol)
{
    int r = blockIdx.x;
    int bt = r >> 10, pix = r & 1023;
    int y = pix >> 5, x = pix & 31;
    int c = threadIdx.x;
    float qv = Q[(long)r * 256 + c];
    float sc[9];
    #pragma unroll
    for (int n = 0; n < 9; n++) {
        int dy = n / 3 - 1, dx = n % 3 - 1;
        int ny = y + dy, nx = x + dx;
        bool ok = ((unsigned)ny < 32u) && ((unsigned)nx < 32u);
        float p = 0.f;
        if (ok) p = qv * K[(((long)(bt << 10) + (ny << 5) + nx) << 8) + c];
        #pragma unroll
        for (int o = 16; o; o >>= 1) p += __shfl_xor_sync(~0u, p, o);
        sc[n] = ok ? p * SCALE : -1e9f;
    }
    float mx = sc[0];
    #pragma unroll
    for (int n = 1; n < 9; n++) mx = fmaxf(mx, sc[n]);
    float den = 0.f;
    #pragma unroll
    for (int n = 0; n < 9; n++) { sc[n] = expf(sc[n] - mx); den += sc[n]; }
    float inv = 1.f / den;
    float acc = 0.f;
    #pragma unroll
    for (int n = 0; n < 9; n++) {
        int dy = n / 3 - 1, dx = n % 3 - 1;
        int ny = y + dy, nx = x + dx;
        if (((unsigned)ny < 32u) && ((unsigned)nx < 32u))
            acc += sc[n] * inv * V[(((long)(bt << 10) + (ny << 5) + nx) << 8) + c];
    }
    __nv_bfloat16 h, l; split_bf16(acc, h, l);
    Oh[(long)r * 256 + c] = h;
    Ol[(long)r * 256 + c] = l;
}

// ---------------- copy CLS/last frame (t=8) query -> X ----------------------
__global__ void copy8_kernel(const float* __restrict__ q, float* __restrict__ X)
{
    long idx = (long)blockIdx.x * 256 + threadIdx.x;
    int b = (int)(idx >> 18);
    long rem = idx & 262143;
    long off = ((long)(b * 9 + 8)) * 262144 + rem;
    X[off] = q[off];
}

// ---------------- Temporal attention + fused RoPE ---------------------------
// block=(b,hw,h) 288 thr; warp=tq, lane=dim within head.
__global__ void tattn_kernel(const float* __restrict__ Q, const float* __restrict__ K,
                             const float* __restrict__ V, const unsigned char* __restrict__ mask,
                             __nv_bfloat16* __restrict__ Oh, __nv_bfloat16* __restrict__ Ol)
{
    int blk = blockIdx.x;
    int h = blk & 7, hw = (blk >> 3) & 1023, b = blk >> 13;
    int tq = threadIdx.x >> 5, lane = threadIdx.x & 31;
    int col = (h << 5) + lane;
    int i = lane & 15;
    float invf = exp2f(-(float)i * 0.83048202372184058696f); // 2*log2(1e4)/32
    long base = ((long)b * TQN) << 10;
    long qrow = base + ((long)tq << 10) + hw;

    float qv = Q[qrow * 256 + col];
    float snq, csq; sincosf((float)tq * invf, &snq, &csq);
    float qp = __shfl_xor_sync(~0u, qv, 16);
    float qr = (lane < 16) ? (qv * csq - qp * snq) : (qp * snq + qv * csq);

    float sc[9];
    #pragma unroll
    for (int tk = 0; tk < 9; tk++) {
        long krow = base + ((long)tk << 10) + hw;
        float kv = K[krow * 256 + col];
        float snk, csk; sincosf((float)tk * invf, &snk, &csk);
        float kp_ = __shfl_xor_sync(~0u, kv, 16);
        float kr = (lane < 16) ? (kv * csk - kp_ * snk) : (kp_ * snk + kv * csk);
        float p = qr * kr;
        #pragma unroll
        for (int o = 16; o; o >>= 1) p += __shfl_xor_sync(~0u, p, o);
        sc[tk] = mask[tq * 9 + tk] ? -1e9f : p * SCALE;
    }
    float mx = sc[0];
    #pragma unroll
    for (int t = 1; t < 9; t++) mx = fmaxf(mx, sc[t]);
    float den = 0.f;
    #pragma unroll
    for (int t = 0; t < 9; t++) { sc[t] = expf(sc[t] - mx); den += sc[t]; }
    float inv = 1.f / den;
    float acc = 0.f;
    #pragma unroll
    for (int tk = 0; tk < 9; tk++) {
        long krow = base + ((long)tk << 10) + hw;
        acc += sc[tk] * inv * V[krow * 256 + col];
    }
    __nv_bfloat16 hh, ll; split_bf16(acc, hh, ll);
    Oh[qrow * 256 + col] = hh;
    Ol[qrow * 256 + col] = ll;
}

// ---------------- CLS frame (t=0): parallel reduce + broadcast --------------
__global__ void cls_reduce_kernel(const float* __restrict__ X, float* __restrict__ P)
{
    int chunk = blockIdx.x, b = blockIdx.y, d = threadIdx.x;
    long base = (long)(b * 9) * HWN * DIMN + (long)chunk * 128 * DIMN;
    float s = 0.f;
    #pragma unroll 4
    for (int hw = 0; hw < 128; hw++) s += X[base + (long)hw * DIMN + d];
    P[((long)b * 8 + chunk) * DIMN + d] = s;
}
__global__ void cls_bcast_kernel(const float* __restrict__ P, float* __restrict__ X)
{
    int chunk = blockIdx.x, b = blockIdx.y, d = threadIdx.x;
    float s = 0.f;
    #pragma unroll
    for (int c = 0; c < 8; c++) s += P[((long)b * 8 + c) * DIMN + d];
    s *= (1.f / 1024.f);
    long base = (long)(b * 9) * HWN * DIMN + (long)chunk * 128 * DIMN;
    #pragma unroll 4
    for (int hw = 0; hw < 128; hw++) X[base + (long)hw * DIMN + d] = s;
}

// ---------------- launch ----------------------------------------------------
#define O_SWQ 0
#define O_SWK 65536
#define O_SWV 131072
#define O_SWO 196608
#define O_TWQ 262144
#define O_TWK 327680
#define O_TWV 393216
#define O_TWO 458752
#define O_W1  524288
#define O_W2  786432

extern "C" void kernel_launch(void* const* d_in, const int* in_sizes, int n_in,
                              void* d_out, int out_size)
{
    const float* query = (const float*)d_in[0];
    const unsigned char* tmask = (const unsigned char*)d_in[2];
    const float* sln_g = (const float*)d_in[3];
    const float* sln_b = (const float*)d_in[4];
    const float* s_wq = (const float*)d_in[5];  const float* s_bq = (const float*)d_in[6];
    const float* s_wk = (const float*)d_in[7];  const float* s_bk = (const float*)d_in[8];
    const float* s_wv = (const float*)d_in[9];  const float* s_bv = (const float*)d_in[10];
    const float* s_wo = (const float*)d_in[11]; const float* s_bo = (const float*)d_in[12];
    const float* tln_g = (const float*)d_in[13];
    const float* tln_b = (const float*)d_in[14];
    const float* t_wq = (const float*)d_in[15]; const float* t_bq = (const float*)d_in[16];
    const float* t_wk = (const float*)d_in[17]; const float* t_bk = (const float*)d_in[18];
    const float* t_wv = (const float*)d_in[19]; const float* t_bv = (const float*)d_in[20];
    const float* t_wo = (const float*)d_in[21]; const float* t_bo = (const float*)d_in[22];
    const float* mln_g = (const float*)d_in[23];
    const float* mln_b = (const float*)d_in[24];
    const float* w1 = (const float*)d_in[25];   const float* b1 = (const float*)d_in[26];
    const float* w2 = (const float*)d_in[27];   const float* b2 = (const float*)d_in[28];
    float* out = (float*)d_out;

    float *q, *k, *v, *x, *clsp;
    __nv_bfloat16 *xnh, *xnl, *oh, *ol, *hh, *hl, *wth, *wtl;
    cudaGetSymbolAddress((void**)&q,  g_q);
    cudaGetSymbolAddress((void**)&k,  g_k);
    cudaGetSymbolAddress((void**)&v,  g_v);
    cudaGetSymbolAddress((void**)&x,  g_x);
    cudaGetSymbolAddress((void**)&clsp, g_clsp);
    cudaGetSymbolAddress((void**)&xnh, g_xnh);
    cudaGetSymbolAddress((void**)&xnl, g_xnl);
    cudaGetSymbolAddress((void**)&oh,  g_oh);
    cudaGetSymbolAddress((void**)&ol,  g_ol);
    cudaGetSymbolAddress((void**)&hh,  g_hh);
    cudaGetSymbolAddress((void**)&hl,  g_hl);
    cudaGetSymbolAddress((void**)&wth, g_wth);
    cudaGetSymbolAddress((void**)&wtl, g_wtl);

    cudaFuncSetAttribute(mmagemm, cudaFuncAttributeMaxDynamicSharedMemorySize, MMA_SMEM);

    // ---- all weights: transpose + split, one launch ----
    wsplit_all<<<1024, dim3(32, 8)>>>(s_wq, s_wk, s_wv, s_wo, t_wq, t_wk, t_wv, t_wo,
                                      w1, w2, wth, wtl);

    // ---- spatial block ----
    ln_kernel<<<NROWS_SP, 256>>>(query, sln_g, sln_b, xnh, xnl, 1);
    mmagemm<<<dim3(2, NROWS_SP/128), 256, MMA_SMEM>>>(xnh, xnl, wth+O_SWQ, wtl+O_SWQ, s_bq, nullptr, q, nullptr, nullptr, 256, 256, 0, 0);
    mmagemm<<<dim3(2, NROWS_SP/128), 256, MMA_SMEM>>>(xnh, xnl, wth+O_SWK, wtl+O_SWK, s_bk, nullptr, k, nullptr, nullptr, 256, 256, 0, 0);
    mmagemm<<<dim3(2, NROWS_SP/128), 256, MMA_SMEM>>>(xnh, xnl, wth+O_SWV, wtl+O_SWV, s_bv, nullptr, v, nullptr, nullptr, 256, 256, 0, 0);
    sattn_kernel<<<NROWS_SP, 256>>>(q, k, v, oh, ol);
    mmagemm<<<dim3(2, NROWS_SP/128), 256, MMA_SMEM>>>(oh, ol, wth+O_SWO, wtl+O_SWO, s_bo, query, x, nullptr, nullptr, 256, 256, 0, 1);
    copy8_kernel<<<4096, 256>>>(query, x);

    // ---- temporal block ----
    ln_kernel<<<NROWS, 256>>>(x, tln_g, tln_b, xnh, xnl, 0);
    mmagemm<<<dim3(2, NROWS/128), 256, MMA_SMEM>>>(xnh, xnl, wth+O_TWQ, wtl+O_TWQ, t_bq, nullptr, q, nullptr, nullptr, 256, 256, 0, 0);
    mmagemm<<<dim3(2, NROWS/128), 256, MMA_SMEM>>>(xnh, xnl, wth+O_TWK, wtl+O_TWK, t_bk, nullptr, k, nullptr, nullptr, 256, 256, 0, 0);
    mmagemm<<<dim3(2, NROWS/128), 256, MMA_SMEM>>>(xnh, xnl, wth+O_TWV, wtl+O_TWV, t_bv, nullptr, v, nullptr, nullptr, 256, 256, 0, 0);
    tattn_kernel<<<32768, 288>>>(q, k, v, tmask, oh, ol);
    mmagemm<<<dim3(2, NROWS/128), 256, MMA_SMEM>>>(oh, ol, wth+O_TWO, wtl+O_TWO, t_bo, x, x, nullptr, nullptr, 256, 256, 0, 0);

    // ---- CLS average ----
    cls_reduce_kernel<<<dim3(8, 4), 256>>>(x, clsp);
    cls_bcast_kernel<<<dim3(8, 4), 256>>>(clsp, x);

    // ---- MLP ----
    ln_kernel<<<NROWS, 256>>>(x, mln_g, mln_b, xnh, xnl, 0);
    mmagemm<<<dim3(8, NROWS/128), 256, MMA_SMEM>>>(xnh, xnl, wth+O_W1, wtl+O_W1, b1, nullptr, nullptr, hh, hl, 1024, 256, 1, 0);
    mmagemm<<<dim3(2, NROWS/128), 256, MMA_SMEM>>>(hh, hl, wth+O_W2, wtl+O_W2, b2, x, out, nullptr, nullptr, 256, 1024, 0, 0);
}

// round 9
// speedup vs baseline: 2.1490x; 1.1546x over previous
#include <cuda_runtime.h>
#include <cuda_bf16.h>
#include <math.h>
#include <stdint.h>

// Problem constants
#define BATCH 4
#define TQN   9
#define TFR   8
#define HWN   1024
#define DIMN  256
#define NHN   8
#define DHN   32
#define MLPD  1024
#define NROWS    (BATCH*TQN*HWN)   // 36864
#define NROWS_SP (BATCH*TFR*HWN)   // 32768
#define SCALE 0.17677669529663687f

// ---------------- scratch (static device memory; no allocations) -----------
__device__ __align__(16) float g_q [NROWS*DIMN];
__device__ __align__(16) float g_k [NROWS*DIMN];
__device__ __align__(16) float g_v [NROWS*DIMN];
__device__ __align__(16) float g_x [NROWS*DIMN];
__device__ __align__(16) float g_clsp[BATCH*8*DIMN];
__device__ __align__(16) __nv_bfloat16 g_xnh[NROWS*DIMN];
__device__ __align__(16) __nv_bfloat16 g_xnl[NROWS*DIMN];
__device__ __align__(16) __nv_bfloat16 g_oh [NROWS*DIMN];
__device__ __align__(16) __nv_bfloat16 g_ol [NROWS*DIMN];
__device__ __align__(16) __nv_bfloat16 g_hh [(long)NROWS*MLPD];
__device__ __align__(16) __nv_bfloat16 g_hl [(long)NROWS*MLPD];
__device__ __align__(16) __nv_bfloat16 g_wth[1048576];
__device__ __align__(16) __nv_bfloat16 g_wtl[1048576];

// ---------------- helpers ----------------------------------------------
__device__ __forceinline__ uint32_t s2u(const void* p) {
    uint32_t a;
    asm("{ .reg .u64 t; cvta.to.shared.u64 t, %1; cvt.u32.u64 %0, t; }" : "=r"(a) : "l"(p));
    return a;
}
__device__ __forceinline__ void ldsm4(uint32_t* r, uint32_t addr) {
    asm volatile("ldmatrix.sync.aligned.m8n8.x4.shared.b16 {%0,%1,%2,%3}, [%4];"
                 : "=r"(r[0]), "=r"(r[1]), "=r"(r[2]), "=r"(r[3]) : "r"(addr));
}
__device__ __forceinline__ void mma16816(float* d, const uint32_t* a, const uint32_t* b) {
    asm volatile("mma.sync.aligned.m16n8k16.row.col.f32.bf16.bf16.f32 "
                 "{%0,%1,%2,%3}, {%4,%5,%6,%7}, {%8,%9}, {%0,%1,%2,%3};"
                 : "+f"(d[0]), "+f"(d[1]), "+f"(d[2]), "+f"(d[3])
                 : "r"(a[0]), "r"(a[1]), "r"(a[2]), "r"(a[3]), "r"(b[0]), "r"(b[1]));
}
__device__ __forceinline__ void cpa16(uint32_t sm, const void* g) {
    asm volatile("cp.async.cg.shared.global [%0], [%1], 16;" :: "r"(sm), "l"(g));
}
__device__ __forceinline__ void split_bf16(float v, __nv_bfloat16& h, __nv_bfloat16& l) {
    h = __float2bfloat16(v);
    l = __float2bfloat16(v - __bfloat162float(h));
}

// ---------------- all-weights transpose + hi/lo split (one launch) ----------
__global__ void wsplit_all(const float* s0, const float* s1, const float* s2, const float* s3,
                           const float* s4, const float* s5, const float* s6, const float* s7,
                           const float* s8, const float* s9,
                           __nv_bfloat16* __restrict__ Th, __nv_bfloat16* __restrict__ Tl)
{
    __shared__ float tile[32][33];
    int t = blockIdx.x;
    const float* W; long dst; int K, M, mtile, ktile;
    if (t < 512) {
        int j = t >> 6, wi = t & 63;
        K = 256; M = 256; mtile = wi & 7; ktile = wi >> 3;
        dst = (long)j * 65536;
        switch (j) {
            case 0: W = s0; break; case 1: W = s1; break; case 2: W = s2; break;
            case 3: W = s3; break; case 4: W = s4; break; case 5: W = s5; break;
            case 6: W = s6; break; default: W = s7; break;
        }
    } else if (t < 768) {
        int wi = t - 512;
        K = 256; M = 1024; mtile = wi & 31; ktile = wi >> 5;
        dst = 524288; W = s8;
    } else {
        int wi = t - 768;
        K = 1024; M = 256; mtile = wi & 7; ktile = wi >> 3;
        dst = 786432; W = s9;
    }
    int mb = mtile * 32, kb = ktile * 32;
    int tx = threadIdx.x, ty = threadIdx.y;
    #pragma unroll
    for (int i = 0; i < 32; i += 8)
        tile[ty + i][tx] = W[(long)(kb + ty + i) * M + mb + tx];
    __syncthreads();
    #pragma unroll
    for (int i = 0; i < 32; i += 8) {
        float v = tile[tx][ty + i];
        __nv_bfloat16 h, l; split_bf16(v, h, l);
        long o = dst + (long)(mb + ty + i) * K + kb + tx;
        Th[o] = h; Tl[o] = l;
    }
}

// ---------------- mma.sync bf16 split-precision GEMM ------------------------
// BK=32, hi/lo packed per 128B row, 2-stage cp.async pipeline, 2 CTAs/SM.
// mode 0: fp32 out (+res). mode 1: gelu -> split bf16 outh/outl.
// mode 2: QKV triple — out selected by column group (stride 256 each).
#define MMA_SMEM 65536

__global__ void __launch_bounds__(256, 2)
mmagemm(const __nv_bfloat16* __restrict__ Ah, const __nv_bfloat16* __restrict__ Al,
        const __nv_bfloat16* __restrict__ Wh, const __nv_bfloat16* __restrict__ Wl,
        const float* __restrict__ bias, const float* __restrict__ biasB,
        const float* __restrict__ biasC, const float* __restrict__ res,
        float* __restrict__ out, float* __restrict__ outB, float* __restrict__ outC,
        __nv_bfloat16* __restrict__ outh, __nv_bfloat16* __restrict__ outl,
        int M, int K, int mode, int remap)
{
    extern __shared__ __align__(1024) char smem[];
    uint32_t sb = s2u(smem);
    int tid = threadIdx.x, wid = tid >> 5, lane = tid & 31;
    int wm = (wid & 1) * 64, wn = (wid >> 1) * 32;

    long rowBase = (long)blockIdx.y * 128;
    int  colBase = blockIdx.x * 128;
    const __nv_bfloat16* Ahp = Ah + rowBase * K;
    const __nv_bfloat16* Alp = Al + rowBase * K;
    const __nv_bfloat16* Whp = Wh + (long)colBase * K;
    const __nv_bfloat16* Wlp = Wl + (long)colBase * K;

    float acc[4][4][4];
    #pragma unroll
    for (int i = 0; i < 4; i++)
        #pragma unroll
        for (int j = 0; j < 4; j++)
            #pragma unroll
            for (int tt = 0; tt < 4; tt++) acc[i][j][tt] = 0.f;

    int nchunk = K >> 5;

    // stage loader: buffer s, k-offset kbase. A at +0, B at +16384 within stage.
    auto stage = [&](int s, int kbase) {
        uint32_t base = sb + s * 32768;
        #pragma unroll
        for (int i = 0; i < 8; i++) {
            int slot = tid + i * 256;
            int half = slot >> 10;                 // 0 = A, 1 = B  (uniform per i)
            int s2 = slot & 1023;
            int row = s2 >> 3;
            int cch = s2 & 7;                      // 0-3 hi, 4-7 lo
            uint32_t off = row * 128 + cch * 16;
            uint32_t sw = off ^ ((off >> 3) & 0x70);
            long go = (long)row * K + kbase + (cch & 3) * 8;
            const __nv_bfloat16* src = half
                ? ((cch < 4) ? Whp : Wlp) + go
                : ((cch < 4) ? Ahp : Alp) + go;
            cpa16(base + half * 16384 + sw, src);
        }
        asm volatile("cp.async.commit_group;");
    };

    stage(0, 0);
    for (int c = 0; c < nchunk; c++) {
        if (c + 1 < nchunk) {
            stage((c + 1) & 1, (c + 1) << 5);
            asm volatile("cp.async.wait_group 1;" ::: "memory");
        } else {
            asm volatile("cp.async.wait_group 0;" ::: "memory");
        }
        __syncthreads();

        uint32_t abase = sb + (c & 1) * 32768;
        uint32_t bbase = abase + 16384;
        #pragma unroll
        for (int ks = 0; ks < 2; ks++) {
            uint32_t ah[4][4], al[4][4];
            #pragma unroll
            for (int ma = 0; ma < 4; ma++) {
                int row = wm + ma * 16 + (lane & 15);
                int ch  = ks * 2 + (lane >> 4);
                uint32_t off = row * 128 + ch * 16;
                uint32_t swh = off ^ ((off >> 3) & 0x70);
                uint32_t offl = off + 64;
                uint32_t swl = offl ^ ((offl >> 3) & 0x70);
                ldsm4(ah[ma], abase + swh);
                ldsm4(al[ma], abase + swl);
            }
            uint32_t bh[2][4], bl[2][4];
            #pragma unroll
            for (int np = 0; np < 2; np++) {
                int g = lane >> 3;
                int nrow = wn + np * 16 + (g >> 1) * 8 + (lane & 7);
                int ch = ks * 2 + (g & 1);
                uint32_t off = nrow * 128 + ch * 16;
                uint32_t swh = off ^ ((off >> 3) & 0x70);
                uint32_t offl = off + 64;
                uint32_t swl = offl ^ ((offl >> 3) & 0x70);
                ldsm4(bh[np], bbase + swh);
                ldsm4(bl[np], bbase + swl);
            }
            #pragma unroll
            for (int ma = 0; ma < 4; ma++)
                #pragma unroll
                for (int na = 0; na < 4; na++) {
                    const uint32_t* bhp = &bh[na >> 1][(na & 1) * 2];
                    const uint32_t* blp = &bl[na >> 1][(na & 1) * 2];
                    mma16816(acc[ma][na], ah[ma], bhp);
                    mma16816(acc[ma][na], ah[ma], blp);
                    mma16816(acc[ma][na], al[ma], bhp);
                }
        }
        __syncthreads();
    }

    // ---- epilogue ----
    int which = colBase >> 8;                       // for mode 2
    float* op = out; const float* bp = bias;
    if (mode == 2) {
        op = (which == 0) ? out : (which == 1) ? outB : outC;
        bp = (which == 0) ? bias : (which == 1) ? biasB : biasC;
    }
    #pragma unroll
    for (int ma = 0; ma < 4; ma++) {
        #pragma unroll
        for (int half = 0; half < 2; half++) {
            long m = rowBase + wm + ma * 16 + (lane >> 2) + half * 8;
            long om = m;
            if (remap) { int b = (int)(m >> 13), t = (int)((m >> 10) & 7), hw = (int)(m & 1023);
                         om = ((long)(b * 9 + t) << 10) + hw; }
            #pragma unroll
            for (int na = 0; na < 4; na++) {
                int n0 = colBase + wn + na * 8 + (lane & 3) * 2;
                int nc = (mode == 2) ? (n0 & 255) : n0;
                float2 bv = *(const float2*)&bp[nc];
                float2 vv;
                vv.x = acc[ma][na][half * 2 + 0] + bv.x;
                vv.y = acc[ma][na][half * 2 + 1] + bv.y;
                if (mode == 1) {
                    vv.x = 0.5f * vv.x * (1.f + erff(vv.x * 0.70710678118654752f));
                    vv.y = 0.5f * vv.y * (1.f + erff(vv.y * 0.70710678118654752f));
                    __nv_bfloat16 hx, lx, hy, ly;
                    split_bf16(vv.x, hx, lx);
                    split_bf16(vv.y, hy, ly);
                    uint32_t hw_ = ((uint32_t)__bfloat16_as_ushort(hy) << 16) | __bfloat16_as_ushort(hx);
                    uint32_t lw_ = ((uint32_t)__bfloat16_as_ushort(ly) << 16) | __bfloat16_as_ushort(lx);
                    *(uint32_t*)&outh[om * M + n0] = hw_;
                    *(uint32_t*)&outl[om * M + n0] = lw_;
                } else if (mode == 2) {
                    *(float2*)&op[om * 256 + nc] = vv;
                } else {
                    if (res) {
                        float2 rv = *(const float2*)&res[om * M + n0];
                        vv.x += rv.x; vv.y += rv.y;
                    }
                    *(float2*)&op[om * M + n0] = vv;
                }
            }
        }
    }
}

// ---------------- LayerNorm -> split bf16 -----------------------------------
__global__ void ln_kernel(const float* __restrict__ in, const float* __restrict__ g,
                          const float* __restrict__ bta, __nv_bfloat16* __restrict__ outh,
                          __nv_bfloat16* __restrict__ outl, int remap)
{
    int r = blockIdx.x;
    long ir = r;
    if (remap) { int b = r >> 13, t = (r >> 10) & 7, hw = r & 1023;
                 ir = ((long)(b * 9 + t) << 10) + hw; }
    float v = in[ir * DIMN + threadIdx.x];
    __shared__ float sbuf[40];
    float s = v, q = v * v;
    #pragma unroll
    for (int o = 16; o; o >>= 1) { s += __shfl_xor_sync(~0u, s, o); q += __shfl_xor_sync(~0u, q, o); }
    int w = threadIdx.x >> 5;
    if ((threadIdx.x & 31) == 0) { sbuf[w] = s; sbuf[8 + w] = q; }
    __syncthreads();
    if (threadIdx.x < 32) {
        s = (threadIdx.x < 8) ? sbuf[threadIdx.x] : 0.f;
        q = (threadIdx.x < 8) ? sbuf[8 + threadIdx.x] : 0.f;
        #pragma unroll
        for (int o = 4; o; o >>= 1) { s += __shfl_xor_sync(~0u, s, o); q += __shfl_xor_sync(~0u, q, o); }
        if (threadIdx.x == 0) { sbuf[32] = s; sbuf[33] = q; }
    }
    __syncthreads();
    float mean = sbuf[32] * (1.f / 256.f);
    float var  = sbuf[33] * (1.f / 256.f) - mean * mean;
    float vo = (v - mean) * rsqrtf(var + 1e-5f) * g[threadIdx.x] + bta[threadIdx.x];
    __nv_bfloat16 h, l; split_bf16(vo, h, l);
    outh[(long)r * DIMN + threadIdx.x] = h;
    outl[(long)r * DIMN + threadIdx.x] = l;
}

// ---------------- Spatial windowed attention -> split bf16 ------------------
__global__ void sattn_kernel(const float* __restrict__ Q, const float* __restrict__ K,
                             const float* __restrict__ V,
                             __nv_bfloat16* __restrict__ Oh, __nv_bfloat16* __restrict__ Ol)
{
    int r = blockIdx.x;
    int bt = r >> 10, pix = r & 1023;
    int y = pix >> 5, x = pix & 31;
    int c = threadIdx.x;
    float qv = Q[(long)r * 256 + c];
    float sc[9];
    #pragma unroll
    for (int n = 0; n < 9; n++) {
        int dy = n / 3 - 1, dx = n % 3 - 1;
        int ny = y + dy, nx = x + dx;
        bool ok = ((unsigned)ny < 32u) && ((unsigned)nx < 32u);
        float p = 0.f;
        if (ok) p = qv * K[(((long)(bt << 10) + (ny << 5) + nx) << 8) + c];
        #pragma unroll
        for (int o = 16; o; o >>= 1) p += __shfl_xor_sync(~0u, p, o);
        sc[n] = ok ? p * SCALE : -1e9f;
    }
    float mx = sc[0];
    #pragma unroll
    for (int n = 1; n < 9; n++) mx = fmaxf(mx, sc[n]);
    float den = 0.f;
    #pragma unroll
    for (int n = 0; n < 9; n++) { sc[n] = expf(sc[n] - mx); den += sc[n]; }
    float inv = 1.f / den;
    float acc = 0.f;
    #pragma unroll
    for (int n = 0; n < 9; n++) {
        int dy = n / 3 - 1, dx = n % 3 - 1;
        int ny = y + dy, nx = x + dx;
        if (((unsigned)ny < 32u) && ((unsigned)nx < 32u))
            acc += sc[n] * inv * V[(((long)(bt << 10) + (ny << 5) + nx) << 8) + c];
    }
    __nv_bfloat16 h, l; split_bf16(acc, h, l);
    Oh[(long)r * 256 + c] = h;
    Ol[(long)r * 256 + c] = l;
}

// ---------------- copy CLS/last frame (t=8) query -> X ----------------------
__global__ void copy8_kernel(const float* __restrict__ q, float* __restrict__ X)
{
    long idx = (long)blockIdx.x * 256 + threadIdx.x;
    int b = (int)(idx >> 18);
    long rem = idx & 262143;
    long off = ((long)(b * 9 + 8)) * 262144 + rem;
    X[off] = q[off];
}

// ---------------- Temporal attention + fused RoPE ---------------------------
__global__ void tattn_kernel(const float* __restrict__ Q, const float* __restrict__ K,
                             const float* __restrict__ V, const unsigned char* __restrict__ mask,
                             __nv_bfloat16* __restrict__ Oh, __nv_bfloat16* __restrict__ Ol)
{
    int blk = blockIdx.x;
    int h = blk & 7, hw = (blk >> 3) & 1023, b = blk >> 13;
    int tq = threadIdx.x >> 5, lane = threadIdx.x & 31;
    int col = (h << 5) + lane;
    int i = lane & 15;
    float invf = exp2f(-(float)i * 0.83048202372184058696f);
    long base = ((long)b * TQN) << 10;
    long qrow = base + ((long)tq << 10) + hw;

    float qv = Q[qrow * 256 + col];
    float snq, csq; sincosf((float)tq * invf, &snq, &csq);
    float qp = __shfl_xor_sync(~0u, qv, 16);
    float qr = (lane < 16) ? (qv * csq - qp * snq) : (qp * snq + qv * csq);

    float sc[9];
    #pragma unroll
    for (int tk = 0; tk < 9; tk++) {
        long krow = base + ((long)tk << 10) + hw;
        float kv = K[krow * 256 + col];
        float snk, csk; sincosf((float)tk * invf, &snk, &csk);
        float kp_ = __shfl_xor_sync(~0u, kv, 16);
        float kr = (lane < 16) ? (kv * csk - kp_ * snk) : (kp_ * snk + kv * csk);
        float p = qr * kr;
        #pragma unroll
        for (int o = 16; o; o >>= 1) p += __shfl_xor_sync(~0u, p, o);
        sc[tk] = mask[tq * 9 + tk] ? -1e9f : p * SCALE;
    }
    float mx = sc[0];
    #pragma unroll
    for (int t = 1; t < 9; t++) mx = fmaxf(mx, sc[t]);
    float den = 0.f;
    #pragma unroll
    for (int t = 0; t < 9; t++) { sc[t] = expf(sc[t] - mx); den += sc[t]; }
    float inv = 1.f / den;
    float acc = 0.f;
    #pragma unroll
    for (int tk = 0; tk < 9; tk++) {
        long krow = base + ((long)tk << 10) + hw;
        acc += sc[tk] * inv * V[krow * 256 + col];
    }
    __nv_bfloat16 hh, ll; split_bf16(acc, hh, ll);
    Oh[qrow * 256 + col] = hh;
    Ol[qrow * 256 + col] = ll;
}

// ---------------- CLS frame (t=0): parallel reduce + broadcast --------------
__global__ void cls_reduce_kernel(const float* __restrict__ X, float* __restrict__ P)
{
    int chunk = blockIdx.x, b = blockIdx.y, d = threadIdx.x;
    long base = (long)(b * 9) * HWN * DIMN + (long)chunk * 128 * DIMN;
    float s = 0.f;
    #pragma unroll 4
    for (int hw = 0; hw < 128; hw++) s += X[base + (long)hw * DIMN + d];
    P[((long)b * 8 + chunk) * DIMN + d] = s;
}
__global__ void cls_bcast_kernel(const float* __restrict__ P, float* __restrict__ X)
{
    int chunk = blockIdx.x, b = blockIdx.y, d = threadIdx.x;
    float s = 0.f;
    #pragma unroll
    for (int c = 0; c < 8; c++) s += P[((long)b * 8 + c) * DIMN + d];
    s *= (1.f / 1024.f);
    long base = (long)(b * 9) * HWN * DIMN + (long)chunk * 128 * DIMN;
    #pragma unroll 4
    for (int hw = 0; hw < 128; hw++) X[base + (long)hw * DIMN + d] = s;
}

// ---------------- launch ----------------------------------------------------
#define O_SQKV 0
#define O_SWO 196608
#define O_TQKV 262144
#define O_TWO 458752
#define O_W1  524288
#define O_W2  786432

extern "C" void kernel_launch(void* const* d_in, const int* in_sizes, int n_in,
                              void* d_out, int out_size)
{
    const float* query = (const float*)d_in[0];
    const unsigned char* tmask = (const unsigned char*)d_in[2];
    const float* sln_g = (const float*)d_in[3];
    const float* sln_b = (const float*)d_in[4];
    const float* s_wq = (const float*)d_in[5];  const float* s_bq = (const float*)d_in[6];
    const float* s_wk = (const float*)d_in[7];  const float* s_bk = (const float*)d_in[8];
    const float* s_wv = (const float*)d_in[9];  const float* s_bv = (const float*)d_in[10];
    const float* s_wo = (const float*)d_in[11]; const float* s_bo = (const float*)d_in[12];
    const float* tln_g = (const float*)d_in[13];
    const float* tln_b = (const float*)d_in[14];
    const float* t_wq = (const float*)d_in[15]; const float* t_bq = (const float*)d_in[16];
    const float* t_wk = (const float*)d_in[17]; const float* t_bk = (const float*)d_in[18];
    const float* t_wv = (const float*)d_in[19]; const float* t_bv = (const float*)d_in[20];
    const float* t_wo = (const float*)d_in[21]; const float* t_bo = (const float*)d_in[22];
    const float* mln_g = (const float*)d_in[23];
    const float* mln_b = (const float*)d_in[24];
    const float* w1 = (const float*)d_in[25];   const float* b1 = (const float*)d_in[26];
    const float* w2 = (const float*)d_in[27];   const float* b2 = (const float*)d_in[28];
    float* out = (float*)d_out;

    float *q, *k, *v, *x, *clsp;
    __nv_bfloat16 *xnh, *xnl, *oh, *ol, *hh, *hl, *wth, *wtl;
    cudaGetSymbolAddress((void**)&q,  g_q);
    cudaGetSymbolAddress((void**)&k,  g_k);
    cudaGetSymbolAddress((void**)&v,  g_v);
    cudaGetSymbolAddress((void**)&x,  g_x);
    cudaGetSymbolAddress((void**)&clsp, g_clsp);
    cudaGetSymbolAddress((void**)&xnh, g_xnh);
    cudaGetSymbolAddress((void**)&xnl, g_xnl);
    cudaGetSymbolAddress((void**)&oh,  g_oh);
    cudaGetSymbolAddress((void**)&ol,  g_ol);
    cudaGetSymbolAddress((void**)&hh,  g_hh);
    cudaGetSymbolAddress((void**)&hl,  g_hl);
    cudaGetSymbolAddress((void**)&wth, g_wth);
    cudaGetSymbolAddress((void**)&wtl, g_wtl);

    cudaFuncSetAttribute(mmagemm, cudaFuncAttributeMaxDynamicSharedMemorySize, MMA_SMEM);

    wsplit_all<<<1024, dim3(32, 8)>>>(s_wq, s_wk, s_wv, s_wo, t_wq, t_wk, t_wv, t_wo,
                                      w1, w2, wth, wtl);

    // ---- spatial block ----
    ln_kernel<<<NROWS_SP, 256>>>(query, sln_g, sln_b, xnh, xnl, 1);
    mmagemm<<<dim3(6, NROWS_SP/128), 256, MMA_SMEM>>>(xnh, xnl, wth+O_SQKV, wtl+O_SQKV,
        s_bq, s_bk, s_bv, nullptr, q, k, v, nullptr, nullptr, 256, 256, 2, 0);
    sattn_kernel<<<NROWS_SP, 256>>>(q, k, v, oh, ol);
    mmagemm<<<dim3(2, NROWS_SP/128), 256, MMA_SMEM>>>(oh, ol, wth+O_SWO, wtl+O_SWO,
        s_bo, nullptr, nullptr, query, x, nullptr, nullptr, nullptr, nullptr, 256, 256, 0, 1);
    copy8_kernel<<<4096, 256>>>(query, x);

    // ---- temporal block ----
    ln_kernel<<<NROWS, 256>>>(x, tln_g, tln_b, xnh, xnl, 0);
    mmagemm<<<dim3(6, NROWS/128), 256, MMA_SMEM>>>(xnh, xnl, wth+O_TQKV, wtl+O_TQKV,
        t_bq, t_bk, t_bv, nullptr, q, k, v, nullptr, nullptr, 256, 256, 2, 0);
    tattn_kernel<<<32768, 288>>>(q, k, v, tmask, oh, ol);
    mmagemm<<<dim3(2, NROWS/128), 256, MMA_SMEM>>>(oh, ol, wth+O_TWO, wtl+O_TWO,
        t_bo, nullptr, nullptr, x, x, nullptr, nullptr, nullptr, nullptr, 256, 256, 0, 0);

    // ---- CLS average ----
    cls_reduce_kernel<<<dim3(8, 4), 256>>>(x, clsp);
    cls_bcast_kernel<<<dim3(8, 4), 256>>>(clsp, x);

    // ---- MLP ----
    ln_kernel<<<NROWS, 256>>>(x, mln_g, mln_b, xnh, xnl, 0);
    mmagemm<<<dim3(8, NROWS/128), 256, MMA_SMEM>>>(xnh, xnl, wth+O_W1, wtl+O_W1,
        b1, nullptr, nullptr, nullptr, nullptr, nullptr, nullptr, hh, hl, 1024, 256, 1, 0);
    mmagemm<<<dim3(2, NROWS/128), 256, MMA_SMEM>>>(hh, hl, wth+O_W2, wtl+O_W2,
        b2, nullptr, nullptr, x, out, nullptr, nullptr, nullptr, nullptr, 256, 1024, 0, 0);
}